// round 2
// baseline (speedup 1.0000x reference)
#include <cuda_runtime.h>
#include <math.h>

typedef unsigned long long ull;
#define CLAMPV 10000.0f

// ---------------- static scratch ----------------
__device__ float g_xproj[16777216];   // [BL*T,128]
__device__ float g_qbuf [16777216];
__device__ float g_recv [16777216];
__device__ float g_k15[245760];       // [BL][15][128]
__device__ float g_v15[245760];
__device__ float g_rproj[40960];      // [32*10][128]
__device__ float g_buf[163840];       // [BL][2][10][64]

// ---------------- helpers ----------------
__device__ __forceinline__ ull ffma2(ull a, ull b, ull c) {
    ull d; asm("fma.rn.f32x2 %0, %1, %2, %3;" : "=l"(d) : "l"(a), "l"(b), "l"(c)); return d;
}
__device__ __forceinline__ ull pack2(float lo, float hi) {
    ull r; asm("mov.b64 %0, {%1, %2};" : "=l"(r) : "f"(lo), "f"(hi)); return r;
}
__device__ __forceinline__ void unpack2(ull v, float& lo, float& hi) {
    asm("mov.b64 {%0, %1}, %2;" : "=f"(lo), "=f"(hi) : "l"(v));
}
union F4U { float4 f; ull u[2]; };
__device__ __forceinline__ float gelu_exact(float x) {
    return 0.5f * x * (1.0f + erff(x * 0.7071067811865475f));
}
__device__ __forceinline__ float redsum16(float v) {
    v += __shfl_xor_sync(0xffffffffu, v, 1);
    v += __shfl_xor_sync(0xffffffffu, v, 2);
    v += __shfl_xor_sync(0xffffffffu, v, 4);
    v += __shfl_xor_sync(0xffffffffu, v, 8);
    return v;
}

// ============ fused MLP(128->512->128) + residual + LayerNorm(s) ============
// MODE 0: in = x [B,T,L,D] (gathered); residual = gathered row; out = x_proj, LN(ga,ba)
// MODE 1: in = recv (contig); residual = x_proj; LN(ga,ba) then LN(gb,bb); scatter to [B,T,L,D]
// 64 rows/block, 256 threads, 8 hidden chunks of 64.
#define SMEM_FUSED (45888 * 4)
template <int MODE>
__global__ __launch_bounds__(256, 1) void fused_mlp_ln_kernel(
    const float* __restrict__ in, const float* __restrict__ resid,
    const float* __restrict__ w1, const float* __restrict__ b1,
    const float* __restrict__ w2, const float* __restrict__ b2,
    const float* __restrict__ ga, const float* __restrict__ ba,
    const float* __restrict__ gb, const float* __restrict__ bb,
    float* __restrict__ out)
{
    extern __shared__ float sm[];
    float* XsT = sm;            // [k:128][r:68]
    float* W1d = sm + 8704;     // [k:128][2c:128] duplicated
    float* W2d = sm + 25088;    // [c:64][2n:256] duplicated
    float* HsT = sm + 41472;    // [c:64][r:68]
    float* b1s = sm + 45824;    // [64]

    const int tid = threadIdx.x;
    const int R0 = blockIdx.x * 64;

    // stage input rows transposed
#pragma unroll
    for (int i = 0; i < 32; i++) {
        int idx = tid + i * 256;
        int r = idx >> 7, k = idx & 127;
        int Rg = R0 + r, grow;
        if (MODE == 0) {
            int bl = Rg >> 10, t = Rg & 1023;
            grow = (((bl >> 5) << 10) + t) * 32 + (bl & 31);
        } else grow = Rg;
        XsT[k * 68 + r] = in[grow * 128 + k];
    }

    const int tx = tid & 15, ty = tid >> 4;
    const int r0 = ty * 4;

    ull acc[2][8];
#pragma unroll
    for (int j = 0; j < 8; j++) {
        float bv = __ldg(&b2[tx + 16 * j]);
        acc[0][j] = pack2(bv, bv); acc[1][j] = acc[0][j];
    }

    for (int ch = 0; ch < 8; ch++) {
        __syncthreads();
#pragma unroll
        for (int i = 0; i < 32; i++) {       // W1 chunk dup: [128][64 cols]
            int idx = tid + i * 256;
            int k = idx >> 6, c = idx & 63;
            float v = w1[k * 512 + ch * 64 + c];
            *(ull*)(W1d + k * 128 + 2 * c) = pack2(v, v);
        }
#pragma unroll
        for (int i = 0; i < 32; i++) {       // W2 chunk dup: [64][128]
            int idx = tid + i * 256;
            int c = idx >> 7, n = idx & 127;
            float v = w2[(ch * 64 + c) * 128 + n];
            *(ull*)(W2d + c * 256 + 2 * n) = pack2(v, v);
        }
        if (tid < 64) b1s[tid] = b1[ch * 64 + tid];
        __syncthreads();

        // GEMM1: H[64rows][64cols] = X @ W1chunk, cols = tx+16j
        ull h2[2][4];
#pragma unroll
        for (int j = 0; j < 4; j++) {
            float bv = b1s[tx + 16 * j];
            h2[0][j] = pack2(bv, bv); h2[1][j] = h2[0][j];
        }
#pragma unroll 4
        for (int k = 0; k < 128; k++) {
            F4U a; a.f = *(const float4*)(XsT + k * 68 + r0);
#pragma unroll
            for (int j = 0; j < 4; j++) {
                ull w = *(const ull*)(W1d + k * 128 + 2 * (tx + 16 * j));
                h2[0][j] = ffma2(a.u[0], w, h2[0][j]);
                h2[1][j] = ffma2(a.u[1], w, h2[1][j]);
            }
        }
        __syncthreads();
#pragma unroll
        for (int j = 0; j < 4; j++) {
            int c = tx + 16 * j;
            float v0, v1, v2, v3;
            unpack2(h2[0][j], v0, v1); unpack2(h2[1][j], v2, v3);
            HsT[c * 68 + r0]     = gelu_exact(v0);
            HsT[c * 68 + r0 + 1] = gelu_exact(v1);
            HsT[c * 68 + r0 + 2] = gelu_exact(v2);
            HsT[c * 68 + r0 + 3] = gelu_exact(v3);
        }
        __syncthreads();

        // GEMM2: OUT[64][128] += H @ W2chunk, cols = tx+16j
#pragma unroll 4
        for (int c = 0; c < 64; c++) {
            F4U a; a.f = *(const float4*)(HsT + c * 68 + r0);
#pragma unroll
            for (int j = 0; j < 8; j++) {
                ull w = *(const ull*)(W2d + c * 256 + 2 * (tx + 16 * j));
                acc[0][j] = ffma2(a.u[0], w, acc[0][j]);
                acc[1][j] = ffma2(a.u[1], w, acc[1][j]);
            }
        }
    }

    // ---- epilogue: residual + LN(s) ----
    float vals[4][8];
#pragma unroll
    for (int rp = 0; rp < 2; rp++)
#pragma unroll
        for (int j = 0; j < 8; j++) {
            unpack2(acc[rp][j], vals[2 * rp][j], vals[2 * rp + 1][j]);
        }
    float gan[8], ban[8], gbn[8], bbn[8];
#pragma unroll
    for (int j = 0; j < 8; j++) {
        int c = tx + 16 * j;
        gan[j] = __ldg(&ga[c]); ban[j] = __ldg(&ba[c]);
        gbn[j] = (MODE == 1) ? __ldg(&gb[c]) : 0.f;
        bbn[j] = (MODE == 1) ? __ldg(&bb[c]) : 0.f;
    }
#pragma unroll
    for (int rr = 0; rr < 4; rr++) {
        int r = r0 + rr, Rg = R0 + r;
        float* v = vals[rr];
        if (MODE == 0) {
#pragma unroll
            for (int j = 0; j < 8; j++) v[j] += XsT[(tx + 16 * j) * 68 + r];
        } else {
#pragma unroll
            for (int j = 0; j < 8; j++) v[j] += resid[Rg * 128 + tx + 16 * j];
        }
        float s = 0.f;
#pragma unroll
        for (int j = 0; j < 8; j++) s += v[j];
        float mean = redsum16(s) * 0.0078125f;
        float sq = 0.f;
#pragma unroll
        for (int j = 0; j < 8; j++) { float d = v[j] - mean; sq += d * d; }
        float rstd = rsqrtf(redsum16(sq) * 0.0078125f + 1e-5f);
#pragma unroll
        for (int j = 0; j < 8; j++) v[j] = (v[j] - mean) * rstd * gan[j] + ban[j];

        if (MODE == 0) {
#pragma unroll
            for (int j = 0; j < 8; j++) out[Rg * 128 + tx + 16 * j] = v[j];
        } else {
            float s2 = 0.f;
#pragma unroll
            for (int j = 0; j < 8; j++) s2 += v[j];
            float m2 = redsum16(s2) * 0.0078125f;
            float sq2 = 0.f;
#pragma unroll
            for (int j = 0; j < 8; j++) { float d = v[j] - m2; sq2 += d * d; }
            float rstd2 = rsqrtf(redsum16(sq2) * 0.0078125f + 1e-5f);
            int bl = Rg >> 10, t = Rg & 1023;
            int ob = ((((bl >> 5) << 10) + t) * 32 + (bl & 31)) * 128;
#pragma unroll
            for (int j = 0; j < 8; j++)
                out[ob + tx + 16 * j] = (v[j] - m2) * rstd2 * gbn[j] + bbn[j];
        }
    }
}

// ============ q projection: [131072,128]@[128,128]+b ============
#define SMEM_PROJ (41472 * 4)
__global__ __launch_bounds__(256, 1) void proj_kernel(
    const float* __restrict__ xp, const float* __restrict__ w,
    const float* __restrict__ bias, float* __restrict__ out)
{
    extern __shared__ float sm[];
    float* XsT = sm;            // [128][68]
    float* Wd  = sm + 8704;     // [128][256] dup
    const int tid = threadIdx.x;
    const int R0 = blockIdx.x * 64;
#pragma unroll
    for (int i = 0; i < 32; i++) {
        int idx = tid + i * 256;
        int r = idx >> 7, k = idx & 127;
        XsT[k * 68 + r] = xp[(R0 + r) * 128 + k];
    }
#pragma unroll
    for (int i = 0; i < 64; i++) {
        int idx = tid + i * 256;
        int k = idx >> 7, n = idx & 127;
        float v = w[idx];
        *(ull*)(Wd + k * 256 + 2 * n) = pack2(v, v);
    }
    __syncthreads();
    const int tx = tid & 15, ty = tid >> 4, r0 = ty * 4;
    ull acc[2][8];
#pragma unroll
    for (int j = 0; j < 8; j++) {
        float bv = __ldg(&bias[tx + 16 * j]);
        acc[0][j] = pack2(bv, bv); acc[1][j] = acc[0][j];
    }
#pragma unroll 4
    for (int k = 0; k < 128; k++) {
        F4U a; a.f = *(const float4*)(XsT + k * 68 + r0);
#pragma unroll
        for (int j = 0; j < 8; j++) {
            ull w2 = *(const ull*)(Wd + k * 256 + 2 * (tx + 16 * j));
            acc[0][j] = ffma2(a.u[0], w2, acc[0][j]);
            acc[1][j] = ffma2(a.u[1], w2, acc[1][j]);
        }
    }
#pragma unroll
    for (int rp = 0; rp < 2; rp++)
#pragma unroll
        for (int j = 0; j < 8; j++) {
            float lo, hi; unpack2(acc[rp][j], lo, hi);
            int c = tx + 16 * j;
            out[(R0 + r0 + 2 * rp) * 128 + c] = lo;
            out[(R0 + r0 + 2 * rp + 1) * 128 + c] = hi;
        }
}

// ============ K/V projection, t<15 only ============
#define SMEM_KV (34688 * 4)
__global__ __launch_bounds__(256, 1) void kv_kernel(
    const float* __restrict__ xp,
    const float* __restrict__ wk, const float* __restrict__ bk,
    const float* __restrict__ wv, const float* __restrict__ bv,
    float* __restrict__ k15, float* __restrict__ v15)
{
    extern __shared__ float sm[];
    float* Xs = sm;             // [15][128]
    float* Wks = sm + 1920;
    float* Wvs = sm + 18304;
    const int bl = blockIdx.x, tid = threadIdx.x;
    for (int idx = tid; idx < 1920; idx += 256)
        Xs[idx] = xp[(bl * 1024 + (idx >> 7)) * 128 + (idx & 127)];
    for (int idx = tid; idx < 16384; idx += 256) { Wks[idx] = wk[idx]; Wvs[idx] = wv[idx]; }
    __syncthreads();
    const int m = tid >> 7, n = tid & 127;
    const float* W = m ? Wvs : Wks;
    const float bsv = m ? __ldg(&bv[n]) : __ldg(&bk[n]);
    float* o = m ? v15 : k15;
    for (int t = 0; t < 15; t++) {
        float acc = bsv;
#pragma unroll 8
        for (int k = 0; k < 128; k++) acc += Xs[t * 128 + k] * W[k * 128 + n];
        o[(bl * 15 + t) * 128 + n] = acc;
    }
}

// ============ router projection (320 rows) ============
__global__ void rproj_kernel(const float* __restrict__ router,
                             const float* __restrict__ w,
                             const float* __restrict__ b,
                             float* __restrict__ rp)
{
    __shared__ float rs[128];
    const int row = blockIdx.x, tid = threadIdx.x;
    rs[tid] = router[row * 128 + tid];
    __syncthreads();
    float acc = __ldg(&b[tid]);
#pragma unroll 8
    for (int k = 0; k < 128; k++) acc += rs[k] * w[k * 128 + tid];
    rp[row * 128 + tid] = acc;
}

// ============ buffer attention: q=router_proj[10], keys/values = first 15 ============
__global__ void buffer_kernel(const float* __restrict__ rp,
                              const float* __restrict__ k15,
                              const float* __restrict__ v15,
                              float* __restrict__ buf)
{
    __shared__ float qs[10][64], ks[15][64], vs[15][64], sw[16];
    const int bl = blockIdx.x >> 1, h = blockIdx.x & 1;
    const int tid = threadIdx.x;           // 64
    const int l = bl & 31;
    for (int idx = tid; idx < 640; idx += 64)
        qs[idx >> 6][idx & 63] = rp[(l * 10 + (idx >> 6)) * 128 + h * 64 + (idx & 63)];
    for (int idx = tid; idx < 960; idx += 64) {
        int base = (bl * 15 + (idx >> 6)) * 128 + h * 64 + (idx & 63);
        ks[idx >> 6][idx & 63] = k15[base];
        vs[idx >> 6][idx & 63] = v15[base];
    }
    __syncthreads();
    for (int i = 0; i < 10; i++) {
        int jlo = (i > 5) ? (i - 5) : 0;
        int cnt = i + 5 - jlo + 1;
        if (tid < cnt) {
            float s = 0.f;
            const float* q = qs[i]; const float* kk = ks[jlo + tid];
#pragma unroll 8
            for (int d = 0; d < 64; d++) s += q[d] * kk[d];
            s *= 0.125f;
            sw[tid] = fminf(fmaxf(s, -CLAMPV), CLAMPV);
        }
        __syncthreads();
        float m = -1e30f;
        for (int j = 0; j < cnt; j++) m = fmaxf(m, sw[j]);
        float den = 0.f, o = 0.f;
        for (int j = 0; j < cnt; j++) {
            float p = expf(sw[j] - m);
            den += p;
            o += p * vs[jlo + j][tid];
        }
        buf[((bl * 2 + h) * 10 + i) * 64 + tid] = o / den;
        __syncthreads();
    }
}

// ============ recv attention: q over 10 buffer slots (banded for t<10) ============
__global__ __launch_bounds__(256) void recv_kernel(
    const float* __restrict__ q, const float* __restrict__ buf,
    float* __restrict__ recv)
{
    __shared__ float bufs[640];
    const int bx = blockIdx.x;
    const int bl = bx >> 8, rem = bx & 255;
    const int h = rem >> 7, t0 = (rem & 127) * 8;
    const int tid = threadIdx.x;
    for (int idx = tid; idx < 640; idx += 256)
        bufs[idx] = buf[(bl * 2 + h) * 640 + idx];
    __syncthreads();
    const int t = t0 + (tid >> 5), lane = tid & 31;
    const int qb = (bl * 1024 + t) * 128 + h * 64;
    const float q0 = q[qb + lane], q1 = q[qb + lane + 32];
    float s[10];
#pragma unroll
    for (int j = 0; j < 10; j++) {
        float v = q0 * bufs[j * 64 + lane] + q1 * bufs[j * 64 + lane + 32];
        v += __shfl_xor_sync(0xffffffffu, v, 16);
        v += __shfl_xor_sync(0xffffffffu, v, 8);
        v += __shfl_xor_sync(0xffffffffu, v, 4);
        v += __shfl_xor_sync(0xffffffffu, v, 2);
        v += __shfl_xor_sync(0xffffffffu, v, 1);
        s[j] = fminf(fmaxf(v * 0.125f, -CLAMPV), CLAMPV);
    }
    bool all = (t >= 10);
    float m = -1e30f;
#pragma unroll
    for (int j = 0; j < 10; j++) {
        bool a = all || (j >= t - 5 && j <= t + 5);
        if (a) m = fmaxf(m, s[j]);
    }
    float den = 0.f, o0 = 0.f, o1 = 0.f;
#pragma unroll
    for (int j = 0; j < 10; j++) {
        bool a = all || (j >= t - 5 && j <= t + 5);
        float p = a ? expf(s[j] - m) : 0.f;
        den += p;
        o0 += p * bufs[j * 64 + lane];
        o1 += p * bufs[j * 64 + lane + 32];
    }
    float r = 1.f / den;
    recv[qb + lane] = o0 * r;
    recv[qb + lane + 32] = o1 * r;
}

// ============ launch ============
extern "C" void kernel_launch(void* const* d_in, const int* in_sizes, int n_in,
                              void* d_out, int out_size)
{
    const float* x        = (const float*)d_in[0];
    const float* router   = (const float*)d_in[1];
    const float* w_router = (const float*)d_in[2];
    const float* b_router = (const float*)d_in[3];
    const float* w_k      = (const float*)d_in[4];
    const float* b_k      = (const float*)d_in[5];
    const float* w_v      = (const float*)d_in[6];
    const float* b_v      = (const float*)d_in[7];
    const float* w_q      = (const float*)d_in[8];
    const float* b_q      = (const float*)d_in[9];
    const float* m1w1 = (const float*)d_in[10];
    const float* m1b1 = (const float*)d_in[11];
    const float* m1w2 = (const float*)d_in[12];
    const float* m1b2 = (const float*)d_in[13];
    const float* m2w1 = (const float*)d_in[14];
    const float* m2b1 = (const float*)d_in[15];
    const float* m2w2 = (const float*)d_in[16];
    const float* m2b2 = (const float*)d_in[17];
    const float* g1  = (const float*)d_in[18];
    const float* be1 = (const float*)d_in[19];
    const float* g2  = (const float*)d_in[20];
    const float* be2 = (const float*)d_in[21];
    const float* g3  = (const float*)d_in[22];
    const float* be3 = (const float*)d_in[23];
    float* out = (float*)d_out;

    float *xproj, *qbuf, *recv, *k15, *v15, *rproj, *bufp;
    cudaGetSymbolAddress((void**)&xproj, g_xproj);
    cudaGetSymbolAddress((void**)&qbuf,  g_qbuf);
    cudaGetSymbolAddress((void**)&recv,  g_recv);
    cudaGetSymbolAddress((void**)&k15,   g_k15);
    cudaGetSymbolAddress((void**)&v15,   g_v15);
    cudaGetSymbolAddress((void**)&rproj, g_rproj);
    cudaGetSymbolAddress((void**)&bufp,  g_buf);

    cudaFuncSetAttribute(fused_mlp_ln_kernel<0>, cudaFuncAttributeMaxDynamicSharedMemorySize, SMEM_FUSED);
    cudaFuncSetAttribute(fused_mlp_ln_kernel<1>, cudaFuncAttributeMaxDynamicSharedMemorySize, SMEM_FUSED);
    cudaFuncSetAttribute(proj_kernel, cudaFuncAttributeMaxDynamicSharedMemorySize, SMEM_PROJ);
    cudaFuncSetAttribute(kv_kernel, cudaFuncAttributeMaxDynamicSharedMemorySize, SMEM_KV);

    // 1. x_proj = LN(x + mlp1(x))
    fused_mlp_ln_kernel<0><<<2048, 256, SMEM_FUSED>>>(
        x, nullptr, m1w1, m1b1, m1w2, m1b2, g1, be1, g1, be1, xproj);
    // 2. K/V for t<15
    kv_kernel<<<128, 256, SMEM_KV>>>(xproj, w_k, b_k, w_v, b_v, k15, v15);
    // 3. router projection (l-only)
    rproj_kernel<<<320, 128>>>(router, w_router, b_router, rproj);
    // 4. buffer attention
    buffer_kernel<<<256, 64>>>(rproj, k15, v15, bufp);
    // 5. query projection
    proj_kernel<<<2048, 256, SMEM_PROJ>>>(xproj, w_q, b_q, qbuf);
    // 6. recv attention
    recv_kernel<<<32768, 256>>>(qbuf, bufp, recv);
    // 7. out = LN(LN(x_proj + mlp2(recv)))
    fused_mlp_ln_kernel<1><<<2048, 256, SMEM_FUSED>>>(
        recv, xproj, m2w1, m2b1, m2w2, m2b2, g2, be2, g3, be3, out);
}

// round 3
// speedup vs baseline: 1.5386x; 1.5386x over previous
#include <cuda_runtime.h>
#include <math.h>

typedef unsigned long long ull;
#define CLAMPV 10000.0f

// ---------------- static scratch ----------------
__device__ float g_xproj[16777216];   // [BL*T,128]
__device__ float g_qbuf [16777216];
__device__ float g_recv [16777216];
__device__ float g_k15[245760];       // [BL][15][128]
__device__ float g_v15[245760];
__device__ float g_rproj[40960];      // [32*10][128]
__device__ float g_buf[163840];       // [BL][2][10][64]

// ---------------- helpers ----------------
__device__ __forceinline__ ull ffma2(ull a, ull b, ull c) {
    ull d; asm("fma.rn.f32x2 %0, %1, %2, %3;" : "=l"(d) : "l"(a), "l"(b), "l"(c)); return d;
}
__device__ __forceinline__ ull pack2(float lo, float hi) {
    ull r; asm("mov.b64 %0, {%1, %2};" : "=l"(r) : "f"(lo), "f"(hi)); return r;
}
__device__ __forceinline__ void unpack2(ull v, float& lo, float& hi) {
    asm("mov.b64 {%0, %1}, %2;" : "=f"(lo), "=f"(hi) : "l"(v));
}
union F4U { float4 f; ull u[2]; };
__device__ __forceinline__ float gelu_exact(float x) {
    return 0.5f * x * (1.0f + erff(x * 0.7071067811865475f));
}
__device__ __forceinline__ float redsum16(float v) {
    v += __shfl_xor_sync(0xffffffffu, v, 1);
    v += __shfl_xor_sync(0xffffffffu, v, 2);
    v += __shfl_xor_sync(0xffffffffu, v, 4);
    v += __shfl_xor_sync(0xffffffffu, v, 8);
    return v;
}

// ======================================================================
// fused MLP(128->512->128) + residual + LayerNorm(s)
// MODE 0: in = x [B,T,L,D] gathered; residual = gathered row; LN(ga,ba) -> out
// MODE 1: in = recv; residual = x_proj; LN(ga,ba) then LN(gb,bb); scatter out
// 128 rows/block, 256 threads; hidden chunks of 64; per-thread 8x8 reg tile.
// smem floats: XsT[128k][132r] | W1s[128][64] | W2s[64][128] | HsT[64][132] | b1s[64]
// ======================================================================
#define XsT_OFF 0
#define W1S_OFF 16896
#define W2S_OFF 25088
#define HST_OFF 33280
#define B1S_OFF 41728
#define SMEM_FUSED (41792 * 4)

template <int MODE>
__global__ __launch_bounds__(256, 1) void fused_mlp_ln_kernel(
    const float* __restrict__ in, const float* __restrict__ resid,
    const float* __restrict__ w1, const float* __restrict__ b1,
    const float* __restrict__ w2, const float* __restrict__ b2,
    const float* __restrict__ ga, const float* __restrict__ ba,
    const float* __restrict__ gb, const float* __restrict__ bb,
    float* __restrict__ out)
{
    extern __shared__ float sm[];
    float* XsT = sm + XsT_OFF;
    float* W1s = sm + W1S_OFF;
    float* W2s = sm + W2S_OFF;
    float* HsT = sm + HST_OFF;
    float* b1s = sm + B1S_OFF;

    const int tid = threadIdx.x;
    const int R0 = blockIdx.x * 128;
    const int bl0 = R0 >> 10;         // constant within block
    const int tb0 = R0 & 1023;

    // ---- stage input rows transposed: XsT[k][r] ----
#pragma unroll
    for (int i = 0; i < 16; i++) {
        int idx = tid + i * 256;       // 4096 float4s
        int r = idx >> 5;
        int k4 = (idx & 31) * 4;
        int grow;
        if (MODE == 0) grow = ((((bl0 >> 5) << 10) + tb0 + r) << 5) + (bl0 & 31);
        else grow = R0 + r;
        float4 v = *(const float4*)(in + grow * 128 + k4);
        XsT[(k4 + 0) * 132 + r] = v.x;
        XsT[(k4 + 1) * 132 + r] = v.y;
        XsT[(k4 + 2) * 132 + r] = v.z;
        XsT[(k4 + 3) * 132 + r] = v.w;
    }

    const int cx = tid & 15, ry = tid >> 4;
    const int r0 = ry * 8;          // 8 rows
    const int c8 = cx * 8;          // 8 output cols (GEMM2)
    const int c4 = cx * 4;          // 4 hidden cols (GEMM1)

    // ---- GEMM2 accumulators (persist over chunks), pairs = cols ----
    ull acc[8][4];
    {
        float4 ba0 = *(const float4*)(b2 + c8);
        float4 ba1 = *(const float4*)(b2 + c8 + 4);
        ull i0 = pack2(ba0.x, ba0.y), i1 = pack2(ba0.z, ba0.w);
        ull i2 = pack2(ba1.x, ba1.y), i3 = pack2(ba1.z, ba1.w);
#pragma unroll
        for (int r = 0; r < 8; r++) { acc[r][0] = i0; acc[r][1] = i1; acc[r][2] = i2; acc[r][3] = i3; }
    }

    for (int ch = 0; ch < 8; ch++) {
        __syncthreads();
        // stage W1 chunk [128][64] (natural, no dup)
#pragma unroll
        for (int i = 0; i < 8; i++) {
            int idx = tid + i * 256;           // 2048 float4
            int k = idx >> 4, cc = (idx & 15) * 4;
            *(float4*)(W1s + k * 64 + cc) = *(const float4*)(w1 + k * 512 + ch * 64 + cc);
        }
        // stage W2 chunk [64][128] contiguous
#pragma unroll
        for (int i = 0; i < 8; i++) {
            int idx = tid + i * 256;
            *(float4*)(W2s + idx * 4) = *(const float4*)(w2 + ch * 8192 + idx * 4);
        }
        if (tid < 64) b1s[tid] = b1[ch * 64 + tid];
        __syncthreads();

        // ---- GEMM1: H[128r][64c] = X @ W1chunk ----
        ull h[8][2];
        {
            float4 bv = *(const float4*)(b1s + c4);
            ull i0 = pack2(bv.x, bv.y), i1 = pack2(bv.z, bv.w);
#pragma unroll
            for (int r = 0; r < 8; r++) { h[r][0] = i0; h[r][1] = i1; }
        }
#pragma unroll 2
        for (int k = 0; k < 128; k++) {
            float4 a0 = *(const float4*)(XsT + k * 132 + r0);
            float4 a1 = *(const float4*)(XsT + k * 132 + r0 + 4);
            F4U w; w.f = *(const float4*)(W1s + k * 64 + c4);
            ull pa[8];
            pa[0] = pack2(a0.x, a0.x); pa[1] = pack2(a0.y, a0.y);
            pa[2] = pack2(a0.z, a0.z); pa[3] = pack2(a0.w, a0.w);
            pa[4] = pack2(a1.x, a1.x); pa[5] = pack2(a1.y, a1.y);
            pa[6] = pack2(a1.z, a1.z); pa[7] = pack2(a1.w, a1.w);
#pragma unroll
            for (int r = 0; r < 8; r++) {
                h[r][0] = ffma2(pa[r], w.u[0], h[r][0]);
                h[r][1] = ffma2(pa[r], w.u[1], h[r][1]);
            }
        }
        // gelu + store HsT[c][r]
#pragma unroll
        for (int cp = 0; cp < 2; cp++)
#pragma unroll
            for (int r = 0; r < 8; r++) {
                float lo, hi; unpack2(h[r][cp], lo, hi);
                HsT[(c4 + 2 * cp) * 132 + r0 + r]     = gelu_exact(lo);
                HsT[(c4 + 2 * cp + 1) * 132 + r0 + r] = gelu_exact(hi);
            }
        __syncthreads();

        // ---- GEMM2: OUT[128r][128c] += H @ W2chunk ----
#pragma unroll 2
        for (int c = 0; c < 64; c++) {
            float4 a0 = *(const float4*)(HsT + c * 132 + r0);
            float4 a1 = *(const float4*)(HsT + c * 132 + r0 + 4);
            F4U w0, w1v;
            w0.f  = *(const float4*)(W2s + c * 128 + c8);
            w1v.f = *(const float4*)(W2s + c * 128 + c8 + 4);
            ull pa[8];
            pa[0] = pack2(a0.x, a0.x); pa[1] = pack2(a0.y, a0.y);
            pa[2] = pack2(a0.z, a0.z); pa[3] = pack2(a0.w, a0.w);
            pa[4] = pack2(a1.x, a1.x); pa[5] = pack2(a1.y, a1.y);
            pa[6] = pack2(a1.z, a1.z); pa[7] = pack2(a1.w, a1.w);
#pragma unroll
            for (int r = 0; r < 8; r++) {
                acc[r][0] = ffma2(pa[r], w0.u[0], acc[r][0]);
                acc[r][1] = ffma2(pa[r], w0.u[1], acc[r][1]);
                acc[r][2] = ffma2(pa[r], w1v.u[0], acc[r][2]);
                acc[r][3] = ffma2(pa[r], w1v.u[1], acc[r][3]);
            }
        }
    }

    // ---- epilogue: residual + LN(s) ----
    float gan[8], ban[8], gbn[8], bbn[8];
#pragma unroll
    for (int j = 0; j < 8; j++) {
        gan[j] = __ldg(&ga[c8 + j]); ban[j] = __ldg(&ba[c8 + j]);
        gbn[j] = (MODE == 1) ? __ldg(&gb[c8 + j]) : 0.f;
        bbn[j] = (MODE == 1) ? __ldg(&bb[c8 + j]) : 0.f;
    }
#pragma unroll
    for (int r = 0; r < 8; r++) {
        int rl = r0 + r, Rg = R0 + rl;
        float v[8];
#pragma unroll
        for (int cp = 0; cp < 4; cp++) unpack2(acc[r][cp], v[2 * cp], v[2 * cp + 1]);
        if (MODE == 0) {
#pragma unroll
            for (int j = 0; j < 8; j++) v[j] += XsT[(c8 + j) * 132 + rl];
        } else {
            float4 u0 = *(const float4*)(resid + Rg * 128 + c8);
            float4 u1 = *(const float4*)(resid + Rg * 128 + c8 + 4);
            v[0] += u0.x; v[1] += u0.y; v[2] += u0.z; v[3] += u0.w;
            v[4] += u1.x; v[5] += u1.y; v[6] += u1.z; v[7] += u1.w;
        }
        float s = 0.f;
#pragma unroll
        for (int j = 0; j < 8; j++) s += v[j];
        float mean = redsum16(s) * 0.0078125f;
        float sq = 0.f;
#pragma unroll
        for (int j = 0; j < 8; j++) { float d = v[j] - mean; sq += d * d; }
        float rstd = rsqrtf(redsum16(sq) * 0.0078125f + 1e-5f);
#pragma unroll
        for (int j = 0; j < 8; j++) v[j] = (v[j] - mean) * rstd * gan[j] + ban[j];

        if (MODE == 0) {
            float4 o0 = make_float4(v[0], v[1], v[2], v[3]);
            float4 o1 = make_float4(v[4], v[5], v[6], v[7]);
            *(float4*)(out + Rg * 128 + c8) = o0;
            *(float4*)(out + Rg * 128 + c8 + 4) = o1;
        } else {
            float s2 = 0.f;
#pragma unroll
            for (int j = 0; j < 8; j++) s2 += v[j];
            float m2 = redsum16(s2) * 0.0078125f;
            float sq2 = 0.f;
#pragma unroll
            for (int j = 0; j < 8; j++) { float d = v[j] - m2; sq2 += d * d; }
            float rstd2 = rsqrtf(redsum16(sq2) * 0.0078125f + 1e-5f);
            int bl = Rg >> 10, t = Rg & 1023;
            int ob = ((((bl >> 5) << 10) + t) * 32 + (bl & 31)) * 128;
            float4 o0, o1;
            o0.x = (v[0] - m2) * rstd2 * gbn[0] + bbn[0];
            o0.y = (v[1] - m2) * rstd2 * gbn[1] + bbn[1];
            o0.z = (v[2] - m2) * rstd2 * gbn[2] + bbn[2];
            o0.w = (v[3] - m2) * rstd2 * gbn[3] + bbn[3];
            o1.x = (v[4] - m2) * rstd2 * gbn[4] + bbn[4];
            o1.y = (v[5] - m2) * rstd2 * gbn[5] + bbn[5];
            o1.z = (v[6] - m2) * rstd2 * gbn[6] + bbn[6];
            o1.w = (v[7] - m2) * rstd2 * gbn[7] + bbn[7];
            *(float4*)(out + ob + c8) = o0;
            *(float4*)(out + ob + c8 + 4) = o1;
        }
    }
}

// ======================================================================
// q projection: [131072,128]@[128,128]+b ; 128 rows/block, 8x8 tiles
// smem: XsT[128][132] | Ws[128][128]
// ======================================================================
#define SMEM_PROJ (33280 * 4)
__global__ __launch_bounds__(256, 1) void proj_kernel(
    const float* __restrict__ xp, const float* __restrict__ w,
    const float* __restrict__ bias, float* __restrict__ out)
{
    extern __shared__ float sm[];
    float* XsT = sm;
    float* Ws  = sm + 16896;
    const int tid = threadIdx.x;
    const int R0 = blockIdx.x * 128;
#pragma unroll
    for (int i = 0; i < 16; i++) {
        int idx = tid + i * 256;
        int r = idx >> 5;
        int k4 = (idx & 31) * 4;
        float4 v = *(const float4*)(xp + (R0 + r) * 128 + k4);
        XsT[(k4 + 0) * 132 + r] = v.x;
        XsT[(k4 + 1) * 132 + r] = v.y;
        XsT[(k4 + 2) * 132 + r] = v.z;
        XsT[(k4 + 3) * 132 + r] = v.w;
    }
#pragma unroll
    for (int i = 0; i < 16; i++) {
        int idx = tid + i * 256;
        *(float4*)(Ws + idx * 4) = *(const float4*)(w + idx * 4);
    }
    __syncthreads();

    const int cx = tid & 15, ry = tid >> 4;
    const int r0 = ry * 8, c8 = cx * 8;
    ull acc[8][4];
    {
        float4 ba0 = *(const float4*)(bias + c8);
        float4 ba1 = *(const float4*)(bias + c8 + 4);
        ull i0 = pack2(ba0.x, ba0.y), i1 = pack2(ba0.z, ba0.w);
        ull i2 = pack2(ba1.x, ba1.y), i3 = pack2(ba1.z, ba1.w);
#pragma unroll
        for (int r = 0; r < 8; r++) { acc[r][0] = i0; acc[r][1] = i1; acc[r][2] = i2; acc[r][3] = i3; }
    }
#pragma unroll 2
    for (int k = 0; k < 128; k++) {
        float4 a0 = *(const float4*)(XsT + k * 132 + r0);
        float4 a1 = *(const float4*)(XsT + k * 132 + r0 + 4);
        F4U w0, w1v;
        w0.f  = *(const float4*)(Ws + k * 128 + c8);
        w1v.f = *(const float4*)(Ws + k * 128 + c8 + 4);
        ull pa[8];
        pa[0] = pack2(a0.x, a0.x); pa[1] = pack2(a0.y, a0.y);
        pa[2] = pack2(a0.z, a0.z); pa[3] = pack2(a0.w, a0.w);
        pa[4] = pack2(a1.x, a1.x); pa[5] = pack2(a1.y, a1.y);
        pa[6] = pack2(a1.z, a1.z); pa[7] = pack2(a1.w, a1.w);
#pragma unroll
        for (int r = 0; r < 8; r++) {
            acc[r][0] = ffma2(pa[r], w0.u[0], acc[r][0]);
            acc[r][1] = ffma2(pa[r], w0.u[1], acc[r][1]);
            acc[r][2] = ffma2(pa[r], w1v.u[0], acc[r][2]);
            acc[r][3] = ffma2(pa[r], w1v.u[1], acc[r][3]);
        }
    }
#pragma unroll
    for (int r = 0; r < 8; r++) {
        float v[8];
#pragma unroll
        for (int cp = 0; cp < 4; cp++) unpack2(acc[r][cp], v[2 * cp], v[2 * cp + 1]);
        float4 o0 = make_float4(v[0], v[1], v[2], v[3]);
        float4 o1 = make_float4(v[4], v[5], v[6], v[7]);
        *(float4*)(out + (R0 + r0 + r) * 128 + c8) = o0;
        *(float4*)(out + (R0 + r0 + r) * 128 + c8 + 4) = o1;
    }
}

// ============ K/V projection, t<15 only ============
#define SMEM_KV (34688 * 4)
__global__ __launch_bounds__(256, 1) void kv_kernel(
    const float* __restrict__ xp,
    const float* __restrict__ wk, const float* __restrict__ bk,
    const float* __restrict__ wv, const float* __restrict__ bv,
    float* __restrict__ k15, float* __restrict__ v15)
{
    extern __shared__ float sm[];
    float* Xs = sm;             // [15][128]
    float* Wks = sm + 1920;
    float* Wvs = sm + 18304;
    const int bl = blockIdx.x, tid = threadIdx.x;
    for (int idx = tid; idx < 1920; idx += 256)
        Xs[idx] = xp[(bl * 1024 + (idx >> 7)) * 128 + (idx & 127)];
    for (int idx = tid; idx < 16384; idx += 256) { Wks[idx] = wk[idx]; Wvs[idx] = wv[idx]; }
    __syncthreads();
    const int m = tid >> 7, n = tid & 127;
    const float* W = m ? Wvs : Wks;
    const float bsv = m ? __ldg(&bv[n]) : __ldg(&bk[n]);
    float* o = m ? v15 : k15;
    for (int t = 0; t < 15; t++) {
        float acc = bsv;
#pragma unroll 8
        for (int k = 0; k < 128; k++) acc += Xs[t * 128 + k] * W[k * 128 + n];
        o[(bl * 15 + t) * 128 + n] = acc;
    }
}

// ============ router projection (320 rows) ============
__global__ void rproj_kernel(const float* __restrict__ router,
                             const float* __restrict__ w,
                             const float* __restrict__ b,
                             float* __restrict__ rp)
{
    __shared__ float rs[128];
    const int row = blockIdx.x, tid = threadIdx.x;
    rs[tid] = router[row * 128 + tid];
    __syncthreads();
    float acc = __ldg(&b[tid]);
#pragma unroll 8
    for (int k = 0; k < 128; k++) acc += rs[k] * w[k * 128 + tid];
    rp[row * 128 + tid] = acc;
}

// ============ buffer attention: q=router_proj[10], keys/values = first 15 ============
__global__ void buffer_kernel(const float* __restrict__ rp,
                              const float* __restrict__ k15,
                              const float* __restrict__ v15,
                              float* __restrict__ buf)
{
    __shared__ float qs[10][64], ks[15][64], vs[15][64], sw[16];
    const int bl = blockIdx.x >> 1, h = blockIdx.x & 1;
    const int tid = threadIdx.x;           // 64
    const int l = bl & 31;
    for (int idx = tid; idx < 640; idx += 64)
        qs[idx >> 6][idx & 63] = rp[(l * 10 + (idx >> 6)) * 128 + h * 64 + (idx & 63)];
    for (int idx = tid; idx < 960; idx += 64) {
        int base = (bl * 15 + (idx >> 6)) * 128 + h * 64 + (idx & 63);
        ks[idx >> 6][idx & 63] = k15[base];
        vs[idx >> 6][idx & 63] = v15[base];
    }
    __syncthreads();
    for (int i = 0; i < 10; i++) {
        int jlo = (i > 5) ? (i - 5) : 0;
        int cnt = i + 5 - jlo + 1;
        if (tid < cnt) {
            float s = 0.f;
            const float* q = qs[i]; const float* kk = ks[jlo + tid];
#pragma unroll 8
            for (int d = 0; d < 64; d++) s += q[d] * kk[d];
            s *= 0.125f;
            sw[tid] = fminf(fmaxf(s, -CLAMPV), CLAMPV);
        }
        __syncthreads();
        float m = -1e30f;
        for (int j = 0; j < cnt; j++) m = fmaxf(m, sw[j]);
        float den = 0.f, o = 0.f;
        for (int j = 0; j < cnt; j++) {
            float p = expf(sw[j] - m);
            den += p;
            o += p * vs[jlo + j][tid];
        }
        buf[((bl * 2 + h) * 10 + i) * 64 + tid] = o / den;
        __syncthreads();
    }
}

// ============ recv attention: q over 10 buffer slots (banded for t<10) ============
__global__ __launch_bounds__(256) void recv_kernel(
    const float* __restrict__ q, const float* __restrict__ buf,
    float* __restrict__ recv)
{
    __shared__ float bufs[640];
    const int bx = blockIdx.x;
    const int bl = bx >> 8, rem = bx & 255;
    const int h = rem >> 7, t0 = (rem & 127) * 8;
    const int tid = threadIdx.x;
    for (int idx = tid; idx < 640; idx += 256)
        bufs[idx] = buf[(bl * 2 + h) * 640 + idx];
    __syncthreads();
    const int t = t0 + (tid >> 5), lane = tid & 31;
    const int qb = (bl * 1024 + t) * 128 + h * 64;
    const float q0 = q[qb + lane], q1 = q[qb + lane + 32];
    float s[10];
#pragma unroll
    for (int j = 0; j < 10; j++) {
        float v = q0 * bufs[j * 64 + lane] + q1 * bufs[j * 64 + lane + 32];
        v += __shfl_xor_sync(0xffffffffu, v, 16);
        v += __shfl_xor_sync(0xffffffffu, v, 8);
        v += __shfl_xor_sync(0xffffffffu, v, 4);
        v += __shfl_xor_sync(0xffffffffu, v, 2);
        v += __shfl_xor_sync(0xffffffffu, v, 1);
        s[j] = fminf(fmaxf(v * 0.125f, -CLAMPV), CLAMPV);
    }
    bool all = (t >= 10);
    float m = -1e30f;
#pragma unroll
    for (int j = 0; j < 10; j++) {
        bool a = all || (j >= t - 5 && j <= t + 5);
        if (a) m = fmaxf(m, s[j]);
    }
    float den = 0.f, o0 = 0.f, o1 = 0.f;
#pragma unroll
    for (int j = 0; j < 10; j++) {
        bool a = all || (j >= t - 5 && j <= t + 5);
        float p = a ? expf(s[j] - m) : 0.f;
        den += p;
        o0 += p * bufs[j * 64 + lane];
        o1 += p * bufs[j * 64 + lane + 32];
    }
    float r = 1.f / den;
    recv[qb + lane] = o0 * r;
    recv[qb + lane + 32] = o1 * r;
}

// ============ launch ============
extern "C" void kernel_launch(void* const* d_in, const int* in_sizes, int n_in,
                              void* d_out, int out_size)
{
    const float* x        = (const float*)d_in[0];
    const float* router   = (const float*)d_in[1];
    const float* w_router = (const float*)d_in[2];
    const float* b_router = (const float*)d_in[3];
    const float* w_k      = (const float*)d_in[4];
    const float* b_k      = (const float*)d_in[5];
    const float* w_v      = (const float*)d_in[6];
    const float* b_v      = (const float*)d_in[7];
    const float* w_q      = (const float*)d_in[8];
    const float* b_q      = (const float*)d_in[9];
    const float* m1w1 = (const float*)d_in[10];
    const float* m1b1 = (const float*)d_in[11];
    const float* m1w2 = (const float*)d_in[12];
    const float* m1b2 = (const float*)d_in[13];
    const float* m2w1 = (const float*)d_in[14];
    const float* m2b1 = (const float*)d_in[15];
    const float* m2w2 = (const float*)d_in[16];
    const float* m2b2 = (const float*)d_in[17];
    const float* g1  = (const float*)d_in[18];
    const float* be1 = (const float*)d_in[19];
    const float* g2  = (const float*)d_in[20];
    const float* be2 = (const float*)d_in[21];
    const float* g3  = (const float*)d_in[22];
    const float* be3 = (const float*)d_in[23];
    float* out = (float*)d_out;

    float *xproj, *qbuf, *recv, *k15, *v15, *rproj, *bufp;
    cudaGetSymbolAddress((void**)&xproj, g_xproj);
    cudaGetSymbolAddress((void**)&qbuf,  g_qbuf);
    cudaGetSymbolAddress((void**)&recv,  g_recv);
    cudaGetSymbolAddress((void**)&k15,   g_k15);
    cudaGetSymbolAddress((void**)&v15,   g_v15);
    cudaGetSymbolAddress((void**)&rproj, g_rproj);
    cudaGetSymbolAddress((void**)&bufp,  g_buf);

    cudaFuncSetAttribute(fused_mlp_ln_kernel<0>, cudaFuncAttributeMaxDynamicSharedMemorySize, SMEM_FUSED);
    cudaFuncSetAttribute(fused_mlp_ln_kernel<1>, cudaFuncAttributeMaxDynamicSharedMemorySize, SMEM_FUSED);
    cudaFuncSetAttribute(proj_kernel, cudaFuncAttributeMaxDynamicSharedMemorySize, SMEM_PROJ);
    cudaFuncSetAttribute(kv_kernel, cudaFuncAttributeMaxDynamicSharedMemorySize, SMEM_KV);

    // 1. x_proj = LN(x + mlp1(x))
    fused_mlp_ln_kernel<0><<<1024, 256, SMEM_FUSED>>>(
        x, nullptr, m1w1, m1b1, m1w2, m1b2, g1, be1, g1, be1, xproj);
    // 2. K/V for t<15
    kv_kernel<<<128, 256, SMEM_KV>>>(xproj, w_k, b_k, w_v, b_v, k15, v15);
    // 3. router projection (l-only)
    rproj_kernel<<<320, 128>>>(router, w_router, b_router, rproj);
    // 4. buffer attention
    buffer_kernel<<<256, 64>>>(rproj, k15, v15, bufp);
    // 5. query projection
    proj_kernel<<<1024, 256, SMEM_PROJ>>>(xproj, w_q, b_q, qbuf);
    // 6. recv attention
    recv_kernel<<<32768, 256>>>(qbuf, bufp, recv);
    // 7. out = LN(LN(x_proj + mlp2(recv)))
    fused_mlp_ln_kernel<1><<<1024, 256, SMEM_FUSED>>>(
        recv, xproj, m2w1, m2b1, m2w2, m2b2, g2, be2, g3, be3, out);
}

// round 5
// speedup vs baseline: 2.5846x; 1.6798x over previous
#include <cuda_runtime.h>
#include <cuda_bf16.h>
#include <math.h>
#include <stdint.h>

typedef unsigned long long ull;
#define CLAMPV 10000.0f

// ---------------- static scratch ----------------
__device__ float g_xproj[16777216];   // [BL*T,128]
__device__ float g_qbuf [16777216];
__device__ float g_recv [16777216];
__device__ float g_k15[245760];       // [BL][15][128]
__device__ float g_v15[245760];
__device__ float g_rproj[40960];      // [32*10][128]
__device__ float g_buf[163840];       // [BL][2][10][64]

// ---------------- helpers ----------------
__device__ __forceinline__ ull ffma2(ull a, ull b, ull c) {
    ull d; asm("fma.rn.f32x2 %0, %1, %2, %3;" : "=l"(d) : "l"(a), "l"(b), "l"(c)); return d;
}
__device__ __forceinline__ ull pack2(float lo, float hi) {
    ull r; asm("mov.b64 %0, {%1, %2};" : "=l"(r) : "f"(lo), "f"(hi)); return r;
}
__device__ __forceinline__ void unpack2(ull v, float& lo, float& hi) {
    asm("mov.b64 {%0, %1}, %2;" : "=f"(lo), "=f"(hi) : "l"(v));
}
union F4U { float4 f; ull u[2]; };
__device__ __forceinline__ float gelu_exact(float x) {
    return 0.5f * x * (1.0f + erff(x * 0.7071067811865475f));
}
__device__ __forceinline__ uint32_t su32(const void* p) {
    uint32_t a;
    asm("{ .reg .u64 t; cvta.to.shared.u64 t, %1; cvt.u32.u64 %0, t; }" : "=r"(a) : "l"(p));
    return a;
}

// ---------------- legacy tensor-core primitives (sm_80+, OK on sm_103) ----------------
__device__ __forceinline__ void ldmx4(uint32_t* r, uint32_t addr) {
    asm volatile("ldmatrix.sync.aligned.m8n8.x4.shared.b16 {%0,%1,%2,%3}, [%4];"
        : "=r"(r[0]), "=r"(r[1]), "=r"(r[2]), "=r"(r[3]) : "r"(addr));
}
__device__ __forceinline__ void ldmx4t(uint32_t* r, uint32_t addr) {
    asm volatile("ldmatrix.sync.aligned.m8n8.x4.trans.shared.b16 {%0,%1,%2,%3}, [%4];"
        : "=r"(r[0]), "=r"(r[1]), "=r"(r[2]), "=r"(r[3]) : "r"(addr));
}
__device__ __forceinline__ void mma16816(float* c, const uint32_t* a, const uint32_t* b) {
    asm volatile("mma.sync.aligned.m16n8k16.row.col.f32.bf16.bf16.f32 "
        "{%0,%1,%2,%3}, {%4,%5,%6,%7}, {%8,%9}, {%0,%1,%2,%3};"
        : "+f"(c[0]), "+f"(c[1]), "+f"(c[2]), "+f"(c[3])
        : "r"(a[0]), "r"(a[1]), "r"(a[2]), "r"(a[3]), "r"(b[0]), "r"(b[1]));
}

__device__ __forceinline__ void split1(float f, unsigned short& h, unsigned short& l) {
    __nv_bfloat16 bh = __float2bfloat16(f);
    float rem = f - __bfloat162float(bh);
    __nv_bfloat16 bl = __float2bfloat16(rem);
    h = __bfloat16_as_ushort(bh);
    l = __bfloat16_as_ushort(bl);
}
__device__ __forceinline__ void split4(float4 v, ull& hi, ull& lo) {
    unsigned short h0, h1, h2, h3, l0, l1, l2, l3;
    split1(v.x, h0, l0); split1(v.y, h1, l1); split1(v.z, h2, l2); split1(v.w, h3, l3);
    hi = (ull)h0 | ((ull)h1 << 16) | ((ull)h2 << 32) | ((ull)h3 << 48);
    lo = (ull)l0 | ((ull)l1 << 16) | ((ull)l2 << 32) | ((ull)l3 << 48);
}

// ======================================================================
// fused MLP(128->512->128) + residual + LN(s) using mma.sync bf16 3-term
// 128 rows/CTA, 256 threads (8 warps, 2x4 grid of 64x32 tiles), 4 hidden
// chunks of 128. All bf16 tiles: 272B padded rows (conflict-free ldmatrix).
// MODE 0: in = x [B,T,L,D] gathered; residual = same rows; LN(ga,ba) -> out
// MODE 1: in = recv contig; residual = xproj; LN(ga,ba), LN(gb,bb); scatter
// ======================================================================
#define RPITCH 272
#define SM_XHI 0
#define SM_XLO 34816
#define SM_WHI 69632
#define SM_WLO 104448
#define SM_HHI 139264
#define SM_HLO 174080
#define SM_MISC 208896
#define SMEM_TC 210944

template <int MODE>
__global__ __launch_bounds__(256, 1) void fused_mlp_ln_tc(
    const float* __restrict__ in, const float* __restrict__ resid,
    const float* __restrict__ w1, const float* __restrict__ b1,
    const float* __restrict__ w2, const float* __restrict__ b2,
    const float* __restrict__ ga, const float* __restrict__ ba,
    const float* __restrict__ gb, const float* __restrict__ bb,
    float* __restrict__ out)
{
    extern __shared__ char smem[];
    const int tid = threadIdx.x;
    const int wid = tid >> 5;
    const int lane = tid & 31;
    const int R0 = blockIdx.x * 128;
    const int bl0 = R0 >> 10;
    const int bI = bl0 >> 5, lI = bl0 & 31, tb0 = R0 & 1023;
    const uint32_t sb = su32(smem);
    float2* partA = (float2*)(smem + SM_MISC);
    float2* partB = (float2*)(smem + SM_MISC + 1024);

    // ---- stage X hi/lo (contiguous rows) ----
#pragma unroll
    for (int i = 0; i < 16; i++) {
        int idx = tid + i * 256;
        int m = idx >> 5, k4 = (idx & 31) * 4;
        int grow;
        if (MODE == 0) grow = (((bI << 10) + tb0 + m) << 5) + lI;
        else grow = R0 + m;
        float4 v = *(const float4*)(in + grow * 128 + k4);
        ull hi, lo; split4(v, hi, lo);
        *(ull*)(smem + SM_XHI + m * RPITCH + k4 * 2) = hi;
        *(ull*)(smem + SM_XLO + m * RPITCH + k4 * 2) = lo;
    }

    // warp tile: rows [wm, wm+64), cols [wn, wn+32)
    const int wm = (wid >> 2) * 64;
    const int wn = (wid & 3) * 32;
    const int l4 = lane >> 2, lc = (lane & 3) * 2;
    // ldmatrix lane offset (shared by A and B-trans patterns)
    const uint32_t aoffs = (uint32_t)((((lane >> 3) & 1) * 8 + (lane & 7)) * RPITCH
                                      + (((lane >> 4) & 1) * 8) * 2);

    // ---- persistent GEMM2 accumulators (init with b2) ----
    float o[4][4][4];
#pragma unroll
    for (int ni = 0; ni < 4; ni++) {
        int col = wn + ni * 8 + lc;
        float bv0 = __ldg(&b2[col]), bv1 = __ldg(&b2[col + 1]);
#pragma unroll
        for (int mi = 0; mi < 4; mi++) {
            o[mi][ni][0] = bv0; o[mi][ni][1] = bv1;
            o[mi][ni][2] = bv0; o[mi][ni][3] = bv1;
        }
    }

    for (int ch = 0; ch < 4; ch++) {
        __syncthreads();                       // prior GEMM2 done with W/H
        // ---- stage W1 chunk [k=128][n=128] (contiguous) ----
#pragma unroll
        for (int i = 0; i < 16; i++) {
            int idx = tid + i * 256;
            int k = idx >> 5, n4 = (idx & 31) * 4;
            float4 v = *(const float4*)(w1 + k * 512 + ch * 128 + n4);
            ull hi, lo; split4(v, hi, lo);
            *(ull*)(smem + SM_WHI + k * RPITCH + n4 * 2) = hi;
            *(ull*)(smem + SM_WLO + k * RPITCH + n4 * 2) = lo;
        }
        __syncthreads();

        // ---- GEMM1: H[128][128] = X @ W1chunk ----
        float h[4][4][4];
#pragma unroll
        for (int ni = 0; ni < 4; ni++) {
            int col = wn + ni * 8 + lc;
            float bv0 = __ldg(&b1[ch * 128 + col]), bv1 = __ldg(&b1[ch * 128 + col + 1]);
#pragma unroll
            for (int mi = 0; mi < 4; mi++) {
                h[mi][ni][0] = bv0; h[mi][ni][1] = bv1;
                h[mi][ni][2] = bv0; h[mi][ni][3] = bv1;
            }
        }
#pragma unroll 1
        for (int ks = 0; ks < 8; ks++) {
            int k0 = ks * 16;
            uint32_t ah[4][4], al[4][4], bh[8], bl[8];
#pragma unroll
            for (int mi = 0; mi < 4; mi++) {
                ldmx4(ah[mi], sb + SM_XHI + (wm + mi * 16) * RPITCH + k0 * 2 + aoffs);
                ldmx4(al[mi], sb + SM_XLO + (wm + mi * 16) * RPITCH + k0 * 2 + aoffs);
            }
            ldmx4t(bh,     sb + SM_WHI + k0 * RPITCH + wn * 2 + aoffs);
            ldmx4t(bh + 4, sb + SM_WHI + k0 * RPITCH + (wn + 16) * 2 + aoffs);
            ldmx4t(bl,     sb + SM_WLO + k0 * RPITCH + wn * 2 + aoffs);
            ldmx4t(bl + 4, sb + SM_WLO + k0 * RPITCH + (wn + 16) * 2 + aoffs);
#pragma unroll
            for (int mi = 0; mi < 4; mi++)
#pragma unroll
                for (int ni = 0; ni < 4; ni++) {
                    mma16816(h[mi][ni], ah[mi], bh + 2 * ni);
                    mma16816(h[mi][ni], ah[mi], bl + 2 * ni);
                    mma16816(h[mi][ni], al[mi], bh + 2 * ni);
                }
        }
        // ---- gelu + split -> H tiles ----
#pragma unroll
        for (int mi = 0; mi < 4; mi++)
#pragma unroll
            for (int ni = 0; ni < 4; ni++) {
                int r_ = wm + mi * 16 + l4;
                int cb = (wn + ni * 8 + lc) * 2;
                unsigned short h0, l0, h1, l1, h2, l2, h3, l3;
                split1(gelu_exact(h[mi][ni][0]), h0, l0);
                split1(gelu_exact(h[mi][ni][1]), h1, l1);
                split1(gelu_exact(h[mi][ni][2]), h2, l2);
                split1(gelu_exact(h[mi][ni][3]), h3, l3);
                *(uint32_t*)(smem + SM_HHI + r_ * RPITCH + cb) = (uint32_t)h0 | ((uint32_t)h1 << 16);
                *(uint32_t*)(smem + SM_HLO + r_ * RPITCH + cb) = (uint32_t)l0 | ((uint32_t)l1 << 16);
                *(uint32_t*)(smem + SM_HHI + (r_ + 8) * RPITCH + cb) = (uint32_t)h2 | ((uint32_t)h3 << 16);
                *(uint32_t*)(smem + SM_HLO + (r_ + 8) * RPITCH + cb) = (uint32_t)l2 | ((uint32_t)l3 << 16);
            }
        __syncthreads();                       // H ready; W1 reads done
        // ---- stage W2 chunk [k=128][n=128] ----
#pragma unroll
        for (int i = 0; i < 16; i++) {
            int idx = tid + i * 256;
            int k = idx >> 5, n4 = (idx & 31) * 4;
            float4 v = *(const float4*)(w2 + (ch * 128 + k) * 128 + n4);
            ull hi, lo; split4(v, hi, lo);
            *(ull*)(smem + SM_WHI + k * RPITCH + n4 * 2) = hi;
            *(ull*)(smem + SM_WLO + k * RPITCH + n4 * 2) = lo;
        }
        __syncthreads();

        // ---- GEMM2: OUT += H @ W2chunk ----
#pragma unroll 1
        for (int ks = 0; ks < 8; ks++) {
            int k0 = ks * 16;
            uint32_t ah[4][4], al[4][4], bh[8], bl[8];
#pragma unroll
            for (int mi = 0; mi < 4; mi++) {
                ldmx4(ah[mi], sb + SM_HHI + (wm + mi * 16) * RPITCH + k0 * 2 + aoffs);
                ldmx4(al[mi], sb + SM_HLO + (wm + mi * 16) * RPITCH + k0 * 2 + aoffs);
            }
            ldmx4t(bh,     sb + SM_WHI + k0 * RPITCH + wn * 2 + aoffs);
            ldmx4t(bh + 4, sb + SM_WHI + k0 * RPITCH + (wn + 16) * 2 + aoffs);
            ldmx4t(bl,     sb + SM_WLO + k0 * RPITCH + wn * 2 + aoffs);
            ldmx4t(bl + 4, sb + SM_WLO + k0 * RPITCH + (wn + 16) * 2 + aoffs);
#pragma unroll
            for (int mi = 0; mi < 4; mi++)
#pragma unroll
                for (int ni = 0; ni < 4; ni++) {
                    mma16816(o[mi][ni], ah[mi], bh + 2 * ni);
                    mma16816(o[mi][ni], ah[mi], bl + 2 * ni);
                    mma16816(o[mi][ni], al[mi], bh + 2 * ni);
                }
        }
    }

    // ---- epilogue: dump accums to fp32 smem (reuse X region), then LN ----
    __syncthreads();
    float* OB = (float*)(smem + SM_XHI);       // [128][132]
#pragma unroll
    for (int mi = 0; mi < 4; mi++)
#pragma unroll
        for (int ni = 0; ni < 4; ni++) {
            int r_ = wm + mi * 16 + l4;
            int c_ = wn + ni * 8 + lc;
            *(float2*)(OB + r_ * 132 + c_) = make_float2(o[mi][ni][0], o[mi][ni][1]);
            *(float2*)(OB + (r_ + 8) * 132 + c_) = make_float2(o[mi][ni][2], o[mi][ni][3]);
        }
    __syncthreads();

    const int c0 = (wid >= 4) ? 64 : 0;
    const int m = ((wid & 3) << 5) + lane;
    float v[64];
    {
        int grow;
        if (MODE == 0) grow = (((bI << 10) + tb0 + m) << 5) + lI;
        else grow = R0 + m;
        const float* rp = (MODE == 0) ? (in + grow * 128 + c0) : (resid + grow * 128 + c0);
#pragma unroll
        for (int g = 0; g < 16; g++) {
            float4 u = *(const float4*)(rp + 4 * g);
            float4 a = *(const float4*)(OB + m * 132 + c0 + 4 * g);
            v[4 * g + 0] = a.x + u.x;
            v[4 * g + 1] = a.y + u.y;
            v[4 * g + 2] = a.z + u.z;
            v[4 * g + 3] = a.w + u.w;
        }
    }
    {
        float s = 0.f, q = 0.f;
#pragma unroll
        for (int j = 0; j < 64; j++) { s += v[j]; q += v[j] * v[j]; }
        if (c0 == 0) partA[m] = make_float2(s, q); else partB[m] = make_float2(s, q);
    }
    __syncthreads();
    {
        float2 pa = partA[m], pb = partB[m];
        float s = pa.x + pb.x, q = pa.y + pb.y;
        float mean = s * 0.0078125f;
        float rstd = rsqrtf(fmaxf(q * 0.0078125f - mean * mean, 0.f) + 1e-5f);
#pragma unroll
        for (int j = 0; j < 64; j++)
            v[j] = (v[j] - mean) * rstd * __ldg(&ga[c0 + j]) + __ldg(&ba[c0 + j]);
    }
    const int Rg = R0 + m;
    if (MODE == 0) {
#pragma unroll
        for (int g = 0; g < 16; g++)
            *(float4*)(out + Rg * 128 + c0 + 4 * g) =
                make_float4(v[4 * g], v[4 * g + 1], v[4 * g + 2], v[4 * g + 3]);
    } else {
        __syncthreads();
        {
            float s = 0.f, q = 0.f;
#pragma unroll
            for (int j = 0; j < 64; j++) { s += v[j]; q += v[j] * v[j]; }
            if (c0 == 0) partA[m] = make_float2(s, q); else partB[m] = make_float2(s, q);
        }
        __syncthreads();
        float2 pa = partA[m], pb = partB[m];
        float s = pa.x + pb.x, q = pa.y + pb.y;
        float m2 = s * 0.0078125f;
        float rstd2 = rsqrtf(fmaxf(q * 0.0078125f - m2 * m2, 0.f) + 1e-5f);
        int t = tb0 + m;
        int ob = (((bI << 10) + t) * 32 + lI) * 128;
#pragma unroll
        for (int g = 0; g < 16; g++) {
            float4 w;
            w.x = (v[4 * g + 0] - m2) * rstd2 * __ldg(&gb[c0 + 4 * g + 0]) + __ldg(&bb[c0 + 4 * g + 0]);
            w.y = (v[4 * g + 1] - m2) * rstd2 * __ldg(&gb[c0 + 4 * g + 1]) + __ldg(&bb[c0 + 4 * g + 1]);
            w.z = (v[4 * g + 2] - m2) * rstd2 * __ldg(&gb[c0 + 4 * g + 2]) + __ldg(&bb[c0 + 4 * g + 2]);
            w.w = (v[4 * g + 3] - m2) * rstd2 * __ldg(&gb[c0 + 4 * g + 3]) + __ldg(&bb[c0 + 4 * g + 3]);
            *(float4*)(out + ob + c0 + 4 * g) = w;
        }
    }
}

// ======================================================================
// q projection (FFMA2 path, proven in R2)
// ======================================================================
#define SMEM_PROJ (33280 * 4)
__global__ __launch_bounds__(256, 1) void proj_kernel(
    const float* __restrict__ xp, const float* __restrict__ w,
    const float* __restrict__ bias, float* __restrict__ out)
{
    extern __shared__ float sm[];
    float* XsT = sm;
    float* Ws  = sm + 16896;
    const int tid = threadIdx.x;
    const int R0 = blockIdx.x * 128;
#pragma unroll
    for (int i = 0; i < 16; i++) {
        int idx = tid + i * 256;
        int r = idx >> 5;
        int k4 = (idx & 31) * 4;
        float4 v = *(const float4*)(xp + (R0 + r) * 128 + k4);
        XsT[(k4 + 0) * 132 + r] = v.x;
        XsT[(k4 + 1) * 132 + r] = v.y;
        XsT[(k4 + 2) * 132 + r] = v.z;
        XsT[(k4 + 3) * 132 + r] = v.w;
    }
#pragma unroll
    for (int i = 0; i < 16; i++) {
        int idx = tid + i * 256;
        *(float4*)(Ws + idx * 4) = *(const float4*)(w + idx * 4);
    }
    __syncthreads();

    const int cx = tid & 15, ry = tid >> 4;
    const int r0 = ry * 8, c8 = cx * 8;
    ull acc[8][4];
    {
        float4 ba0 = *(const float4*)(bias + c8);
        float4 ba1 = *(const float4*)(bias + c8 + 4);
        ull i0 = pack2(ba0.x, ba0.y), i1 = pack2(ba0.z, ba0.w);
        ull i2 = pack2(ba1.x, ba1.y), i3 = pack2(ba1.z, ba1.w);
#pragma unroll
        for (int r = 0; r < 8; r++) { acc[r][0] = i0; acc[r][1] = i1; acc[r][2] = i2; acc[r][3] = i3; }
    }
#pragma unroll 2
    for (int k = 0; k < 128; k++) {
        float4 a0 = *(const float4*)(XsT + k * 132 + r0);
        float4 a1 = *(const float4*)(XsT + k * 132 + r0 + 4);
        F4U w0, w1v;
        w0.f  = *(const float4*)(Ws + k * 128 + c8);
        w1v.f = *(const float4*)(Ws + k * 128 + c8 + 4);
        ull pa[8];
        pa[0] = pack2(a0.x, a0.x); pa[1] = pack2(a0.y, a0.y);
        pa[2] = pack2(a0.z, a0.z); pa[3] = pack2(a0.w, a0.w);
        pa[4] = pack2(a1.x, a1.x); pa[5] = pack2(a1.y, a1.y);
        pa[6] = pack2(a1.z, a1.z); pa[7] = pack2(a1.w, a1.w);
#pragma unroll
        for (int r = 0; r < 8; r++) {
            acc[r][0] = ffma2(pa[r], w0.u[0], acc[r][0]);
            acc[r][1] = ffma2(pa[r], w0.u[1], acc[r][1]);
            acc[r][2] = ffma2(pa[r], w1v.u[0], acc[r][2]);
            acc[r][3] = ffma2(pa[r], w1v.u[1], acc[r][3]);
        }
    }
#pragma unroll
    for (int r = 0; r < 8; r++) {
        float v[8];
#pragma unroll
        for (int cp = 0; cp < 4; cp++) unpack2(acc[r][cp], v[2 * cp], v[2 * cp + 1]);
        *(float4*)(out + (R0 + r0 + r) * 128 + c8) = make_float4(v[0], v[1], v[2], v[3]);
        *(float4*)(out + (R0 + r0 + r) * 128 + c8 + 4) = make_float4(v[4], v[5], v[6], v[7]);
    }
}

// ============ K/V projection, t<15 only ============
#define SMEM_KV (34688 * 4)
__global__ __launch_bounds__(256, 1) void kv_kernel(
    const float* __restrict__ xp,
    const float* __restrict__ wk, const float* __restrict__ bk,
    const float* __restrict__ wv, const float* __restrict__ bv,
    float* __restrict__ k15, float* __restrict__ v15)
{
    extern __shared__ float sm[];
    float* Xs = sm;
    float* Wks = sm + 1920;
    float* Wvs = sm + 18304;
    const int bl = blockIdx.x, tid = threadIdx.x;
    for (int idx = tid; idx < 1920; idx += 256)
        Xs[idx] = xp[(bl * 1024 + (idx >> 7)) * 128 + (idx & 127)];
    for (int idx = tid; idx < 16384; idx += 256) { Wks[idx] = wk[idx]; Wvs[idx] = wv[idx]; }
    __syncthreads();
    const int m = tid >> 7, n = tid & 127;
    const float* W = m ? Wvs : Wks;
    const float bsv = m ? __ldg(&bv[n]) : __ldg(&bk[n]);
    float* o = m ? v15 : k15;
    for (int t = 0; t < 15; t++) {
        float acc = bsv;
#pragma unroll 8
        for (int k = 0; k < 128; k++) acc += Xs[t * 128 + k] * W[k * 128 + n];
        o[(bl * 15 + t) * 128 + n] = acc;
    }
}

// ============ router projection ============
__global__ void rproj_kernel(const float* __restrict__ router,
                             const float* __restrict__ w,
                             const float* __restrict__ b,
                             float* __restrict__ rp)
{
    __shared__ float rs[128];
    const int row = blockIdx.x, tid = threadIdx.x;
    rs[tid] = router[row * 128 + tid];
    __syncthreads();
    float acc = __ldg(&b[tid]);
#pragma unroll 8
    for (int k = 0; k < 128; k++) acc += rs[k] * w[k * 128 + tid];
    rp[row * 128 + tid] = acc;
}

// ============ buffer attention ============
__global__ void buffer_kernel(const float* __restrict__ rp,
                              const float* __restrict__ k15,
                              const float* __restrict__ v15,
                              float* __restrict__ buf)
{
    __shared__ float qs[10][64], ks[15][64], vs[15][64], sw[16];
    const int bl = blockIdx.x >> 1, h = blockIdx.x & 1;
    const int tid = threadIdx.x;
    const int l = bl & 31;
    for (int idx = tid; idx < 640; idx += 64)
        qs[idx >> 6][idx & 63] = rp[(l * 10 + (idx >> 6)) * 128 + h * 64 + (idx & 63)];
    for (int idx = tid; idx < 960; idx += 64) {
        int base = (bl * 15 + (idx >> 6)) * 128 + h * 64 + (idx & 63);
        ks[idx >> 6][idx & 63] = k15[base];
        vs[idx >> 6][idx & 63] = v15[base];
    }
    __syncthreads();
    for (int i = 0; i < 10; i++) {
        int jlo = (i > 5) ? (i - 5) : 0;
        int cnt = i + 5 - jlo + 1;
        if (tid < cnt) {
            float s = 0.f;
            const float* q = qs[i]; const float* kk = ks[jlo + tid];
#pragma unroll 8
            for (int d = 0; d < 64; d++) s += q[d] * kk[d];
            s *= 0.125f;
            sw[tid] = fminf(fmaxf(s, -CLAMPV), CLAMPV);
        }
        __syncthreads();
        float mm = -1e30f;
        for (int j = 0; j < cnt; j++) mm = fmaxf(mm, sw[j]);
        float den = 0.f, o = 0.f;
        for (int j = 0; j < cnt; j++) {
            float p = expf(sw[j] - mm);
            den += p;
            o += p * vs[jlo + j][tid];
        }
        buf[((bl * 2 + h) * 10 + i) * 64 + tid] = o / den;
        __syncthreads();
    }
}

// ============ recv attention ============
__global__ __launch_bounds__(256) void recv_kernel(
    const float* __restrict__ q, const float* __restrict__ buf,
    float* __restrict__ recv)
{
    __shared__ float bufs[640];
    const int bx = blockIdx.x;
    const int bl = bx >> 8, rem = bx & 255;
    const int h = rem >> 7, t0 = (rem & 127) * 8;
    const int tid = threadIdx.x;
    for (int idx = tid; idx < 640; idx += 256)
        bufs[idx] = buf[(bl * 2 + h) * 640 + idx];
    __syncthreads();
    const int t = t0 + (tid >> 5), lane = tid & 31;
    const int qb = (bl * 1024 + t) * 128 + h * 64;
    const float q0 = q[qb + lane], q1 = q[qb + lane + 32];
    float s[10];
#pragma unroll
    for (int j = 0; j < 10; j++) {
        float v = q0 * bufs[j * 64 + lane] + q1 * bufs[j * 64 + lane + 32];
        v += __shfl_xor_sync(0xffffffffu, v, 16);
        v += __shfl_xor_sync(0xffffffffu, v, 8);
        v += __shfl_xor_sync(0xffffffffu, v, 4);
        v += __shfl_xor_sync(0xffffffffu, v, 2);
        v += __shfl_xor_sync(0xffffffffu, v, 1);
        s[j] = fminf(fmaxf(v * 0.125f, -CLAMPV), CLAMPV);
    }
    bool all = (t >= 10);
    float m = -1e30f;
#pragma unroll
    for (int j = 0; j < 10; j++) {
        bool a = all || (j >= t - 5 && j <= t + 5);
        if (a) m = fmaxf(m, s[j]);
    }
    float den = 0.f, o0 = 0.f, o1 = 0.f;
#pragma unroll
    for (int j = 0; j < 10; j++) {
        bool a = all || (j >= t - 5 && j <= t + 5);
        float p = a ? expf(s[j] - m) : 0.f;
        den += p;
        o0 += p * bufs[j * 64 + lane];
        o1 += p * bufs[j * 64 + lane + 32];
    }
    float r = 1.f / den;
    recv[qb + lane] = o0 * r;
    recv[qb + lane + 32] = o1 * r;
}

// ============ launch ============
extern "C" void kernel_launch(void* const* d_in, const int* in_sizes, int n_in,
                              void* d_out, int out_size)
{
    const float* x        = (const float*)d_in[0];
    const float* router   = (const float*)d_in[1];
    const float* w_router = (const float*)d_in[2];
    const float* b_router = (const float*)d_in[3];
    const float* w_k      = (const float*)d_in[4];
    const float* b_k      = (const float*)d_in[5];
    const float* w_v      = (const float*)d_in[6];
    const float* b_v      = (const float*)d_in[7];
    const float* w_q      = (const float*)d_in[8];
    const float* b_q      = (const float*)d_in[9];
    const float* m1w1 = (const float*)d_in[10];
    const float* m1b1 = (const float*)d_in[11];
    const float* m1w2 = (const float*)d_in[12];
    const float* m1b2 = (const float*)d_in[13];
    const float* m2w1 = (const float*)d_in[14];
    const float* m2b1 = (const float*)d_in[15];
    const float* m2w2 = (const float*)d_in[16];
    const float* m2b2 = (const float*)d_in[17];
    const float* g1  = (const float*)d_in[18];
    const float* be1 = (const float*)d_in[19];
    const float* g2  = (const float*)d_in[20];
    const float* be2 = (const float*)d_in[21];
    const float* g3  = (const float*)d_in[22];
    const float* be3 = (const float*)d_in[23];
    float* out = (float*)d_out;

    float *xproj, *qbuf, *recv, *k15, *v15, *rproj, *bufp;
    cudaGetSymbolAddress((void**)&xproj, g_xproj);
    cudaGetSymbolAddress((void**)&qbuf,  g_qbuf);
    cudaGetSymbolAddress((void**)&recv,  g_recv);
    cudaGetSymbolAddress((void**)&k15,   g_k15);
    cudaGetSymbolAddress((void**)&v15,   g_v15);
    cudaGetSymbolAddress((void**)&rproj, g_rproj);
    cudaGetSymbolAddress((void**)&bufp,  g_buf);

    cudaFuncSetAttribute(fused_mlp_ln_tc<0>, cudaFuncAttributeMaxDynamicSharedMemorySize, SMEM_TC);
    cudaFuncSetAttribute(fused_mlp_ln_tc<1>, cudaFuncAttributeMaxDynamicSharedMemorySize, SMEM_TC);
    cudaFuncSetAttribute(proj_kernel, cudaFuncAttributeMaxDynamicSharedMemorySize, SMEM_PROJ);
    cudaFuncSetAttribute(kv_kernel, cudaFuncAttributeMaxDynamicSharedMemorySize, SMEM_KV);

    // 1. x_proj = LN(x + mlp1(x))
    fused_mlp_ln_tc<0><<<1024, 256, SMEM_TC>>>(
        x, x, m1w1, m1b1, m1w2, m1b2, g1, be1, g1, be1, xproj);
    // 2. K/V for t<15
    kv_kernel<<<128, 256, SMEM_KV>>>(xproj, w_k, b_k, w_v, b_v, k15, v15);
    // 3. router projection
    rproj_kernel<<<320, 128>>>(router, w_router, b_router, rproj);
    // 4. buffer attention
    buffer_kernel<<<256, 64>>>(rproj, k15, v15, bufp);
    // 5. query projection
    proj_kernel<<<1024, 256, SMEM_PROJ>>>(xproj, w_q, b_q, qbuf);
    // 6. recv attention
    recv_kernel<<<32768, 256>>>(qbuf, bufp, recv);
    // 7. out = LN(LN(x_proj + mlp2(recv)))
    fused_mlp_ln_tc<1><<<1024, 256, SMEM_TC>>>(
        recv, xproj, m2w1, m2b1, m2w2, m2b2, g2, be2, g3, be3, out);
}

// round 6
// speedup vs baseline: 3.7457x; 1.4493x over previous
#include <cuda_runtime.h>
#include <cuda_fp16.h>
#include <math.h>
#include <stdint.h>

typedef unsigned long long ull;
#define CLAMPV 10000.0f

// ---------------- static scratch ----------------
__device__ float g_xproj[16777216];   // [BL*T,128]
__device__ float g_qbuf [16777216];
__device__ float g_recv [16777216];
__device__ float g_k15[245760];       // [BL][15][128]
__device__ float g_v15[245760];
__device__ float g_rproj[40960];      // [32*10][128]
__device__ float g_buf[163840];       // [BL][2][10][64]
__device__ __half g_w16[278528];      // m1w1|m1w2|m2w1|m2w2|wq (fp16)

// ---------------- helpers ----------------
__device__ __forceinline__ float gelu_exact(float x) {
    return 0.5f * x * (1.0f + erff(x * 0.7071067811865475f));
}
__device__ __forceinline__ uint32_t su32(const void* p) {
    uint32_t a;
    asm("{ .reg .u64 t; cvta.to.shared.u64 t, %1; cvt.u32.u64 %0, t; }" : "=r"(a) : "l"(p));
    return a;
}

// ---------------- tensor-core primitives (sm_80+, OK on plain sm_103) ----------------
__device__ __forceinline__ void ldmx4(uint32_t* r, uint32_t addr) {
    asm volatile("ldmatrix.sync.aligned.m8n8.x4.shared.b16 {%0,%1,%2,%3}, [%4];"
        : "=r"(r[0]), "=r"(r[1]), "=r"(r[2]), "=r"(r[3]) : "r"(addr));
}
__device__ __forceinline__ void ldmx4t(uint32_t* r, uint32_t addr) {
    asm volatile("ldmatrix.sync.aligned.m8n8.x4.trans.shared.b16 {%0,%1,%2,%3}, [%4];"
        : "=r"(r[0]), "=r"(r[1]), "=r"(r[2]), "=r"(r[3]) : "r"(addr));
}
__device__ __forceinline__ void mma16816(float* c, const uint32_t* a, const uint32_t* b) {
    asm volatile("mma.sync.aligned.m16n8k16.row.col.f32.f16.f16.f32 "
        "{%0,%1,%2,%3}, {%4,%5,%6,%7}, {%8,%9}, {%0,%1,%2,%3};"
        : "+f"(c[0]), "+f"(c[1]), "+f"(c[2]), "+f"(c[3])
        : "r"(a[0]), "r"(a[1]), "r"(a[2]), "r"(a[3]), "r"(b[0]), "r"(b[1]));
}

__device__ __forceinline__ void split1h(float f, unsigned short& h, unsigned short& l) {
    __half hh = __float2half_rn(f);
    float rem = f - __half2float(hh);
    __half hl = __float2half_rn(rem);
    h = __half_as_ushort(hh);
    l = __half_as_ushort(hl);
}
__device__ __forceinline__ void split4h(float4 v, ull& hi, ull& lo) {
    unsigned short h0, h1, h2, h3, l0, l1, l2, l3;
    split1h(v.x, h0, l0); split1h(v.y, h1, l1); split1h(v.z, h2, l2); split1h(v.w, h3, l3);
    hi = (ull)h0 | ((ull)h1 << 16) | ((ull)h2 << 32) | ((ull)h3 << 48);
    lo = (ull)l0 | ((ull)l1 << 16) | ((ull)l2 << 32) | ((ull)l3 << 48);
}

// ============ weight pre-conversion (once per call) ============
__global__ void cvt_weights(const float* __restrict__ w1a, const float* __restrict__ w2a,
                            const float* __restrict__ w1b, const float* __restrict__ w2b,
                            const float* __restrict__ wq, __half* __restrict__ o)
{
    int i = blockIdx.x * 256 + threadIdx.x;
    if (i >= 278528) return;
    float v;
    if (i < 65536) v = w1a[i];
    else if (i < 131072) v = w2a[i - 65536];
    else if (i < 196608) v = w1b[i - 131072];
    else if (i < 262144) v = w2b[i - 196608];
    else v = wq[i - 262144];
    o[i] = __float2half_rn(v);
}

// ======================================================================
// fused MLP(128->512->128) + residual + LN(s), fp16 mma (A split, B single)
// 128 rows/CTA, 256 threads (8 warps, 2x4 grid of 64x32 tiles), 4 hidden
// chunks of 128. 272B-padded rows (conflict-free ldmatrix).
// ======================================================================
#define RPITCH 272
#define SM_XHI 0
#define SM_XLO 34816
#define SM_W   69632
#define SM_HHI 104448
#define SM_HLO 139264
#define SM_MISC 174080
#define SMEM_TC 176128

template <int MODE>
__global__ __launch_bounds__(256, 1) void fused_mlp_ln_tc(
    const float* __restrict__ in, const float* __restrict__ resid,
    const __half* __restrict__ w1h, const float* __restrict__ b1,
    const __half* __restrict__ w2h, const float* __restrict__ b2,
    const float* __restrict__ ga, const float* __restrict__ ba,
    const float* __restrict__ gb, const float* __restrict__ bb,
    float* __restrict__ out)
{
    extern __shared__ char smem[];
    const int tid = threadIdx.x;
    const int wid = tid >> 5;
    const int lane = tid & 31;
    const int R0 = blockIdx.x * 128;
    const int bl0 = R0 >> 10;
    const int bI = bl0 >> 5, lI = bl0 & 31, tb0 = R0 & 1023;
    const uint32_t sb = su32(smem);
    float2* partA = (float2*)(smem + SM_MISC);
    float2* partB = (float2*)(smem + SM_MISC + 1024);

    // ---- stage X hi/lo fp16 ----
#pragma unroll
    for (int i = 0; i < 16; i++) {
        int idx = tid + i * 256;
        int m = idx >> 5, k4 = (idx & 31) * 4;
        int grow;
        if (MODE == 0) grow = (((bI << 10) + tb0 + m) << 5) + lI;
        else grow = R0 + m;
        float4 v = *(const float4*)(in + grow * 128 + k4);
        ull hi, lo; split4h(v, hi, lo);
        *(ull*)(smem + SM_XHI + m * RPITCH + k4 * 2) = hi;
        *(ull*)(smem + SM_XLO + m * RPITCH + k4 * 2) = lo;
    }

    const int wm = (wid >> 2) * 64;
    const int wn = (wid & 3) * 32;
    const int l4 = lane >> 2, lc = (lane & 3) * 2;
    const uint32_t aoffs = (uint32_t)((((lane >> 3) & 1) * 8 + (lane & 7)) * RPITCH
                                      + (((lane >> 4) & 1) * 8) * 2);

    // ---- persistent GEMM2 accumulators ----
    float o[4][4][4];
#pragma unroll
    for (int ni = 0; ni < 4; ni++) {
        int col = wn + ni * 8 + lc;
        float bv0 = __ldg(&b2[col]), bv1 = __ldg(&b2[col + 1]);
#pragma unroll
        for (int mi = 0; mi < 4; mi++) {
            o[mi][ni][0] = bv0; o[mi][ni][1] = bv1;
            o[mi][ni][2] = bv0; o[mi][ni][3] = bv1;
        }
    }

    for (int ch = 0; ch < 4; ch++) {
        __syncthreads();
        // ---- stage W1 chunk [k=128][n=128] fp16 (direct copy) ----
#pragma unroll
        for (int i = 0; i < 8; i++) {
            int idx = tid + i * 256;
            int k = idx >> 4, j = idx & 15;
            *(int4*)(smem + SM_W + k * RPITCH + j * 16) =
                *(const int4*)(w1h + k * 512 + ch * 128 + j * 8);
        }
        __syncthreads();

        // ---- GEMM1: H = X @ W1chunk ----
        float h[4][4][4];
#pragma unroll
        for (int ni = 0; ni < 4; ni++) {
            int col = wn + ni * 8 + lc;
            float bv0 = __ldg(&b1[ch * 128 + col]), bv1 = __ldg(&b1[ch * 128 + col + 1]);
#pragma unroll
            for (int mi = 0; mi < 4; mi++) {
                h[mi][ni][0] = bv0; h[mi][ni][1] = bv1;
                h[mi][ni][2] = bv0; h[mi][ni][3] = bv1;
            }
        }
#pragma unroll 1
        for (int ks = 0; ks < 8; ks++) {
            int k0 = ks * 16;
            uint32_t ah[4][4], al[4][4], b[8];
#pragma unroll
            for (int mi = 0; mi < 4; mi++) {
                ldmx4(ah[mi], sb + SM_XHI + (wm + mi * 16) * RPITCH + k0 * 2 + aoffs);
                ldmx4(al[mi], sb + SM_XLO + (wm + mi * 16) * RPITCH + k0 * 2 + aoffs);
            }
            ldmx4t(b,     sb + SM_W + k0 * RPITCH + wn * 2 + aoffs);
            ldmx4t(b + 4, sb + SM_W + k0 * RPITCH + (wn + 16) * 2 + aoffs);
#pragma unroll
            for (int mi = 0; mi < 4; mi++)
#pragma unroll
                for (int ni = 0; ni < 4; ni++) {
                    mma16816(h[mi][ni], ah[mi], b + 2 * ni);
                    mma16816(h[mi][ni], al[mi], b + 2 * ni);
                }
        }
        // ---- gelu + split -> H tiles ----
#pragma unroll
        for (int mi = 0; mi < 4; mi++)
#pragma unroll
            for (int ni = 0; ni < 4; ni++) {
                int r_ = wm + mi * 16 + l4;
                int cb = (wn + ni * 8 + lc) * 2;
                unsigned short h0, l0, h1, l1, h2, l2, h3, l3;
                split1h(gelu_exact(h[mi][ni][0]), h0, l0);
                split1h(gelu_exact(h[mi][ni][1]), h1, l1);
                split1h(gelu_exact(h[mi][ni][2]), h2, l2);
                split1h(gelu_exact(h[mi][ni][3]), h3, l3);
                *(uint32_t*)(smem + SM_HHI + r_ * RPITCH + cb) = (uint32_t)h0 | ((uint32_t)h1 << 16);
                *(uint32_t*)(smem + SM_HLO + r_ * RPITCH + cb) = (uint32_t)l0 | ((uint32_t)l1 << 16);
                *(uint32_t*)(smem + SM_HHI + (r_ + 8) * RPITCH + cb) = (uint32_t)h2 | ((uint32_t)h3 << 16);
                *(uint32_t*)(smem + SM_HLO + (r_ + 8) * RPITCH + cb) = (uint32_t)l2 | ((uint32_t)l3 << 16);
            }
        __syncthreads();
        // ---- stage W2 chunk ----
#pragma unroll
        for (int i = 0; i < 8; i++) {
            int idx = tid + i * 256;
            int k = idx >> 4, j = idx & 15;
            *(int4*)(smem + SM_W + k * RPITCH + j * 16) =
                *(const int4*)(w2h + (ch * 128 + k) * 128 + j * 8);
        }
        __syncthreads();

        // ---- GEMM2: OUT += H @ W2chunk ----
#pragma unroll 1
        for (int ks = 0; ks < 8; ks++) {
            int k0 = ks * 16;
            uint32_t ah[4][4], al[4][4], b[8];
#pragma unroll
            for (int mi = 0; mi < 4; mi++) {
                ldmx4(ah[mi], sb + SM_HHI + (wm + mi * 16) * RPITCH + k0 * 2 + aoffs);
                ldmx4(al[mi], sb + SM_HLO + (wm + mi * 16) * RPITCH + k0 * 2 + aoffs);
            }
            ldmx4t(b,     sb + SM_W + k0 * RPITCH + wn * 2 + aoffs);
            ldmx4t(b + 4, sb + SM_W + k0 * RPITCH + (wn + 16) * 2 + aoffs);
#pragma unroll
            for (int mi = 0; mi < 4; mi++)
#pragma unroll
                for (int ni = 0; ni < 4; ni++) {
                    mma16816(o[mi][ni], ah[mi], b + 2 * ni);
                    mma16816(o[mi][ni], al[mi], b + 2 * ni);
                }
        }
    }

    // ---- epilogue: dump accums to fp32 smem (reuse X region), then LN ----
    __syncthreads();
    float* OB = (float*)(smem + SM_XHI);       // [128][132]
#pragma unroll
    for (int mi = 0; mi < 4; mi++)
#pragma unroll
        for (int ni = 0; ni < 4; ni++) {
            int r_ = wm + mi * 16 + l4;
            int c_ = wn + ni * 8 + lc;
            *(float2*)(OB + r_ * 132 + c_) = make_float2(o[mi][ni][0], o[mi][ni][1]);
            *(float2*)(OB + (r_ + 8) * 132 + c_) = make_float2(o[mi][ni][2], o[mi][ni][3]);
        }
    __syncthreads();

    const int c0 = (wid >= 4) ? 64 : 0;
    const int m = ((wid & 3) << 5) + lane;
    float v[64];
    {
        int grow;
        if (MODE == 0) grow = (((bI << 10) + tb0 + m) << 5) + lI;
        else grow = R0 + m;
        const float* rp = (MODE == 0) ? (in + grow * 128 + c0) : (resid + grow * 128 + c0);
#pragma unroll
        for (int g = 0; g < 16; g++) {
            float4 u = *(const float4*)(rp + 4 * g);
            float4 a = *(const float4*)(OB + m * 132 + c0 + 4 * g);
            v[4 * g + 0] = a.x + u.x;
            v[4 * g + 1] = a.y + u.y;
            v[4 * g + 2] = a.z + u.z;
            v[4 * g + 3] = a.w + u.w;
        }
    }
    {
        float s = 0.f, q = 0.f;
#pragma unroll
        for (int j = 0; j < 64; j++) { s += v[j]; q += v[j] * v[j]; }
        if (c0 == 0) partA[m] = make_float2(s, q); else partB[m] = make_float2(s, q);
    }
    __syncthreads();
    {
        float2 pa = partA[m], pb = partB[m];
        float s = pa.x + pb.x, q = pa.y + pb.y;
        float mean = s * 0.0078125f;
        float rstd = rsqrtf(fmaxf(q * 0.0078125f - mean * mean, 0.f) + 1e-5f);
#pragma unroll
        for (int j = 0; j < 64; j++)
            v[j] = (v[j] - mean) * rstd * __ldg(&ga[c0 + j]) + __ldg(&ba[c0 + j]);
    }
    const int Rg = R0 + m;
    if (MODE == 0) {
#pragma unroll
        for (int g = 0; g < 16; g++)
            *(float4*)(out + Rg * 128 + c0 + 4 * g) =
                make_float4(v[4 * g], v[4 * g + 1], v[4 * g + 2], v[4 * g + 3]);
    } else {
        __syncthreads();
        {
            float s = 0.f, q = 0.f;
#pragma unroll
            for (int j = 0; j < 64; j++) { s += v[j]; q += v[j] * v[j]; }
            if (c0 == 0) partA[m] = make_float2(s, q); else partB[m] = make_float2(s, q);
        }
        __syncthreads();
        float2 pa = partA[m], pb = partB[m];
        float s = pa.x + pb.x, q = pa.y + pb.y;
        float m2 = s * 0.0078125f;
        float rstd2 = rsqrtf(fmaxf(q * 0.0078125f - m2 * m2, 0.f) + 1e-5f);
        int t = tb0 + m;
        int ob = (((bI << 10) + t) * 32 + lI) * 128;
#pragma unroll
        for (int g = 0; g < 16; g++) {
            float4 w;
            w.x = (v[4 * g + 0] - m2) * rstd2 * __ldg(&gb[c0 + 4 * g + 0]) + __ldg(&bb[c0 + 4 * g + 0]);
            w.y = (v[4 * g + 1] - m2) * rstd2 * __ldg(&gb[c0 + 4 * g + 1]) + __ldg(&bb[c0 + 4 * g + 1]);
            w.z = (v[4 * g + 2] - m2) * rstd2 * __ldg(&gb[c0 + 4 * g + 2]) + __ldg(&bb[c0 + 4 * g + 2]);
            w.w = (v[4 * g + 3] - m2) * rstd2 * __ldg(&gb[c0 + 4 * g + 3]) + __ldg(&bb[c0 + 4 * g + 3]);
            *(float4*)(out + ob + c0 + 4 * g) = w;
        }
    }
}

// ======================================================================
// q projection via fp16 mma (A split, B single), K=128 single pass
// smem: XHI | XLO | W  = 104448 bytes
// ======================================================================
#define SMEM_PROJTC 104448
__global__ __launch_bounds__(256) void proj_tc(
    const float* __restrict__ xp, const __half* __restrict__ wh,
    const float* __restrict__ bias, float* __restrict__ out)
{
    extern __shared__ char smem[];
    const int tid = threadIdx.x;
    const int wid = tid >> 5;
    const int lane = tid & 31;
    const int R0 = blockIdx.x * 128;
    const uint32_t sb = su32(smem);

#pragma unroll
    for (int i = 0; i < 16; i++) {
        int idx = tid + i * 256;
        int m = idx >> 5, k4 = (idx & 31) * 4;
        float4 v = *(const float4*)(xp + (R0 + m) * 128 + k4);
        ull hi, lo; split4h(v, hi, lo);
        *(ull*)(smem + SM_XHI + m * RPITCH + k4 * 2) = hi;
        *(ull*)(smem + SM_XLO + m * RPITCH + k4 * 2) = lo;
    }
#pragma unroll
    for (int i = 0; i < 8; i++) {
        int idx = tid + i * 256;
        int k = idx >> 4, j = idx & 15;
        *(int4*)(smem + SM_W + k * RPITCH + j * 16) = *(const int4*)(wh + k * 128 + j * 8);
    }
    __syncthreads();

    const int wm = (wid >> 2) * 64;
    const int wn = (wid & 3) * 32;
    const int l4 = lane >> 2, lc = (lane & 3) * 2;
    const uint32_t aoffs = (uint32_t)((((lane >> 3) & 1) * 8 + (lane & 7)) * RPITCH
                                      + (((lane >> 4) & 1) * 8) * 2);

    float o[4][4][4];
#pragma unroll
    for (int ni = 0; ni < 4; ni++) {
        int col = wn + ni * 8 + lc;
        float bv0 = __ldg(&bias[col]), bv1 = __ldg(&bias[col + 1]);
#pragma unroll
        for (int mi = 0; mi < 4; mi++) {
            o[mi][ni][0] = bv0; o[mi][ni][1] = bv1;
            o[mi][ni][2] = bv0; o[mi][ni][3] = bv1;
        }
    }
#pragma unroll 1
    for (int ks = 0; ks < 8; ks++) {
        int k0 = ks * 16;
        uint32_t ah[4][4], al[4][4], b[8];
#pragma unroll
        for (int mi = 0; mi < 4; mi++) {
            ldmx4(ah[mi], sb + SM_XHI + (wm + mi * 16) * RPITCH + k0 * 2 + aoffs);
            ldmx4(al[mi], sb + SM_XLO + (wm + mi * 16) * RPITCH + k0 * 2 + aoffs);
        }
        ldmx4t(b,     sb + SM_W + k0 * RPITCH + wn * 2 + aoffs);
        ldmx4t(b + 4, sb + SM_W + k0 * RPITCH + (wn + 16) * 2 + aoffs);
#pragma unroll
        for (int mi = 0; mi < 4; mi++)
#pragma unroll
            for (int ni = 0; ni < 4; ni++) {
                mma16816(o[mi][ni], ah[mi], b + 2 * ni);
                mma16816(o[mi][ni], al[mi], b + 2 * ni);
            }
    }
#pragma unroll
    for (int mi = 0; mi < 4; mi++)
#pragma unroll
        for (int ni = 0; ni < 4; ni++) {
            int r_ = R0 + wm + mi * 16 + l4;
            int c_ = wn + ni * 8 + lc;
            *(float2*)(out + r_ * 128 + c_) = make_float2(o[mi][ni][0], o[mi][ni][1]);
            *(float2*)(out + (r_ + 8) * 128 + c_) = make_float2(o[mi][ni][2], o[mi][ni][3]);
        }
}

// ============ K/V projection, t<15 only ============
#define SMEM_KV (34688 * 4)
__global__ __launch_bounds__(256, 1) void kv_kernel(
    const float* __restrict__ xp,
    const float* __restrict__ wk, const float* __restrict__ bk,
    const float* __restrict__ wv, const float* __restrict__ bv,
    float* __restrict__ k15, float* __restrict__ v15)
{
    extern __shared__ float sm[];
    float* Xs = sm;
    float* Wks = sm + 1920;
    float* Wvs = sm + 18304;
    const int bl = blockIdx.x, tid = threadIdx.x;
    for (int idx = tid; idx < 1920; idx += 256)
        Xs[idx] = xp[(bl * 1024 + (idx >> 7)) * 128 + (idx & 127)];
    for (int idx = tid; idx < 16384; idx += 256) { Wks[idx] = wk[idx]; Wvs[idx] = wv[idx]; }
    __syncthreads();
    const int m = tid >> 7, n = tid & 127;
    const float* W = m ? Wvs : Wks;
    const float bsv = m ? __ldg(&bv[n]) : __ldg(&bk[n]);
    float* o = m ? v15 : k15;
    for (int t = 0; t < 15; t++) {
        float acc = bsv;
#pragma unroll 8
        for (int k = 0; k < 128; k++) acc += Xs[t * 128 + k] * W[k * 128 + n];
        o[(bl * 15 + t) * 128 + n] = acc;
    }
}

// ============ router projection ============
__global__ void rproj_kernel(const float* __restrict__ router,
                             const float* __restrict__ w,
                             const float* __restrict__ b,
                             float* __restrict__ rp)
{
    __shared__ float rs[128];
    const int row = blockIdx.x, tid = threadIdx.x;
    rs[tid] = router[row * 128 + tid];
    __syncthreads();
    float acc = __ldg(&b[tid]);
#pragma unroll 8
    for (int k = 0; k < 128; k++) acc += rs[k] * w[k * 128 + tid];
    rp[row * 128 + tid] = acc;
}

// ============ buffer attention ============
__global__ void buffer_kernel(const float* __restrict__ rp,
                              const float* __restrict__ k15,
                              const float* __restrict__ v15,
                              float* __restrict__ buf)
{
    __shared__ float qs[10][64], ks[15][64], vs[15][64], sw[16];
    const int bl = blockIdx.x >> 1, h = blockIdx.x & 1;
    const int tid = threadIdx.x;
    const int l = bl & 31;
    for (int idx = tid; idx < 640; idx += 64)
        qs[idx >> 6][idx & 63] = rp[(l * 10 + (idx >> 6)) * 128 + h * 64 + (idx & 63)];
    for (int idx = tid; idx < 960; idx += 64) {
        int base = (bl * 15 + (idx >> 6)) * 128 + h * 64 + (idx & 63);
        ks[idx >> 6][idx & 63] = k15[base];
        vs[idx >> 6][idx & 63] = v15[base];
    }
    __syncthreads();
    for (int i = 0; i < 10; i++) {
        int jlo = (i > 5) ? (i - 5) : 0;
        int cnt = i + 5 - jlo + 1;
        if (tid < cnt) {
            float s = 0.f;
            const float* q = qs[i]; const float* kk = ks[jlo + tid];
#pragma unroll 8
            for (int d = 0; d < 64; d++) s += q[d] * kk[d];
            s *= 0.125f;
            sw[tid] = fminf(fmaxf(s, -CLAMPV), CLAMPV);
        }
        __syncthreads();
        float mm = -1e30f;
        for (int j = 0; j < cnt; j++) mm = fmaxf(mm, sw[j]);
        float den = 0.f, o = 0.f;
        for (int j = 0; j < cnt; j++) {
            float p = expf(sw[j] - mm);
            den += p;
            o += p * vs[jlo + j][tid];
        }
        buf[((bl * 2 + h) * 10 + i) * 64 + tid] = o / den;
        __syncthreads();
    }
}

// ============ recv attention ============
__global__ __launch_bounds__(256) void recv_kernel(
    const float* __restrict__ q, const float* __restrict__ buf,
    float* __restrict__ recv)
{
    __shared__ float bufs[640];
    const int bx = blockIdx.x;
    const int bl = bx >> 8, rem = bx & 255;
    const int h = rem >> 7, t0 = (rem & 127) * 8;
    const int tid = threadIdx.x;
    for (int idx = tid; idx < 640; idx += 256)
        bufs[idx] = buf[(bl * 2 + h) * 640 + idx];
    __syncthreads();
    const int t = t0 + (tid >> 5), lane = tid & 31;
    const int qb = (bl * 1024 + t) * 128 + h * 64;
    const float q0 = q[qb + lane], q1 = q[qb + lane + 32];
    float s[10];
#pragma unroll
    for (int j = 0; j < 10; j++) {
        float v = q0 * bufs[j * 64 + lane] + q1 * bufs[j * 64 + lane + 32];
        v += __shfl_xor_sync(0xffffffffu, v, 16);
        v += __shfl_xor_sync(0xffffffffu, v, 8);
        v += __shfl_xor_sync(0xffffffffu, v, 4);
        v += __shfl_xor_sync(0xffffffffu, v, 2);
        v += __shfl_xor_sync(0xffffffffu, v, 1);
        s[j] = fminf(fmaxf(v * 0.125f, -CLAMPV), CLAMPV);
    }
    bool all = (t >= 10);
    float m = -1e30f;
#pragma unroll
    for (int j = 0; j < 10; j++) {
        bool a = all || (j >= t - 5 && j <= t + 5);
        if (a) m = fmaxf(m, s[j]);
    }
    float den = 0.f, o0 = 0.f, o1 = 0.f;
#pragma unroll
    for (int j = 0; j < 10; j++) {
        bool a = all || (j >= t - 5 && j <= t + 5);
        float p = a ? expf(s[j] - m) : 0.f;
        den += p;
        o0 += p * bufs[j * 64 + lane];
        o1 += p * bufs[j * 64 + lane + 32];
    }
    float r = 1.f / den;
    recv[qb + lane] = o0 * r;
    recv[qb + lane + 32] = o1 * r;
}

// ============ launch ============
extern "C" void kernel_launch(void* const* d_in, const int* in_sizes, int n_in,
                              void* d_out, int out_size)
{
    const float* x        = (const float*)d_in[0];
    const float* router   = (const float*)d_in[1];
    const float* w_router = (const float*)d_in[2];
    const float* b_router = (const float*)d_in[3];
    const float* w_k      = (const float*)d_in[4];
    const float* b_k      = (const float*)d_in[5];
    const float* w_v      = (const float*)d_in[6];
    const float* b_v      = (const float*)d_in[7];
    const float* w_q      = (const float*)d_in[8];
    const float* b_q      = (const float*)d_in[9];
    const float* m1w1 = (const float*)d_in[10];
    const float* m1b1 = (const float*)d_in[11];
    const float* m1w2 = (const float*)d_in[12];
    const float* m1b2 = (const float*)d_in[13];
    const float* m2w1 = (const float*)d_in[14];
    const float* m2b1 = (const float*)d_in[15];
    const float* m2w2 = (const float*)d_in[16];
    const float* m2b2 = (const float*)d_in[17];
    const float* g1  = (const float*)d_in[18];
    const float* be1 = (const float*)d_in[19];
    const float* g2  = (const float*)d_in[20];
    const float* be2 = (const float*)d_in[21];
    const float* g3  = (const float*)d_in[22];
    const float* be3 = (const float*)d_in[23];
    float* out = (float*)d_out;

    float *xproj, *qbuf, *recv, *k15, *v15, *rproj, *bufp;
    __half* w16;
    cudaGetSymbolAddress((void**)&xproj, g_xproj);
    cudaGetSymbolAddress((void**)&qbuf,  g_qbuf);
    cudaGetSymbolAddress((void**)&recv,  g_recv);
    cudaGetSymbolAddress((void**)&k15,   g_k15);
    cudaGetSymbolAddress((void**)&v15,   g_v15);
    cudaGetSymbolAddress((void**)&rproj, g_rproj);
    cudaGetSymbolAddress((void**)&bufp,  g_buf);
    cudaGetSymbolAddress((void**)&w16,   g_w16);

    cudaFuncSetAttribute(fused_mlp_ln_tc<0>, cudaFuncAttributeMaxDynamicSharedMemorySize, SMEM_TC);
    cudaFuncSetAttribute(fused_mlp_ln_tc<1>, cudaFuncAttributeMaxDynamicSharedMemorySize, SMEM_TC);
    cudaFuncSetAttribute(proj_tc, cudaFuncAttributeMaxDynamicSharedMemorySize, SMEM_PROJTC);
    cudaFuncSetAttribute(kv_kernel, cudaFuncAttributeMaxDynamicSharedMemorySize, SMEM_KV);

    // 0. weights -> fp16
    cvt_weights<<<1088, 256>>>(m1w1, m1w2, m2w1, m2w2, w_q, w16);
    // 1. x_proj = LN(x + mlp1(x))
    fused_mlp_ln_tc<0><<<1024, 256, SMEM_TC>>>(
        x, x, w16, m1b1, w16 + 65536, m1b2, g1, be1, g1, be1, xproj);
    // 2. K/V for t<15
    kv_kernel<<<128, 256, SMEM_KV>>>(xproj, w_k, b_k, w_v, b_v, k15, v15);
    // 3. router projection
    rproj_kernel<<<320, 128>>>(router, w_router, b_router, rproj);
    // 4. buffer attention
    buffer_kernel<<<256, 64>>>(rproj, k15, v15, bufp);
    // 5. query projection
    proj_tc<<<1024, 256, SMEM_PROJTC>>>(xproj, w16 + 262144, b_q, qbuf);
    // 6. recv attention
    recv_kernel<<<32768, 256>>>(qbuf, bufp, recv);
    // 7. out = LN(LN(x_proj + mlp2(recv)))
    fused_mlp_ln_tc<1><<<1024, 256, SMEM_TC>>>(
        recv, xproj, w16 + 131072, m2b1, w16 + 196608, m2b2, g2, be2, g3, be3, out);
}

// round 7
// speedup vs baseline: 5.4715x; 1.4607x over previous
#include <cuda_runtime.h>
#include <cuda_fp16.h>
#include <math.h>
#include <stdint.h>

typedef unsigned long long ull;
#define CLAMPV 10000.0f

// ---------------- static scratch ----------------
__device__ float g_xproj[16777216];   // [BL*T,128]
__device__ float g_qbuf [16777216];
__device__ float g_k15[245760];       // [BL][15][128]
__device__ float g_v15[245760];
__device__ float g_rproj[40960];      // [32*10][128]
__device__ float g_buf[163840];       // [BL][2][10][64]
__device__ __half g_w16[278528];      // m1w1|m1w2|m2w1|m2w2|wq (fp16)

// ---------------- helpers ----------------
__device__ __forceinline__ float gelu_exact(float x) {
    return 0.5f * x * (1.0f + erff(x * 0.7071067811865475f));
}
__device__ __forceinline__ uint32_t su32(const void* p) {
    uint32_t a;
    asm("{ .reg .u64 t; cvta.to.shared.u64 t, %1; cvt.u32.u64 %0, t; }" : "=r"(a) : "l"(p));
    return a;
}
__device__ __forceinline__ ull pack4h(float4 v) {
    unsigned short a = __half_as_ushort(__float2half_rn(v.x));
    unsigned short b = __half_as_ushort(__float2half_rn(v.y));
    unsigned short c = __half_as_ushort(__float2half_rn(v.z));
    unsigned short d = __half_as_ushort(__float2half_rn(v.w));
    return (ull)a | ((ull)b << 16) | ((ull)c << 32) | ((ull)d << 48);
}

// ---------------- tensor-core primitives (sm_80+, OK on plain sm_103) ----------------
__device__ __forceinline__ void ldmx4(uint32_t* r, uint32_t addr) {
    asm volatile("ldmatrix.sync.aligned.m8n8.x4.shared.b16 {%0,%1,%2,%3}, [%4];"
        : "=r"(r[0]), "=r"(r[1]), "=r"(r[2]), "=r"(r[3]) : "r"(addr));
}
__device__ __forceinline__ void ldmx4t(uint32_t* r, uint32_t addr) {
    asm volatile("ldmatrix.sync.aligned.m8n8.x4.trans.shared.b16 {%0,%1,%2,%3}, [%4];"
        : "=r"(r[0]), "=r"(r[1]), "=r"(r[2]), "=r"(r[3]) : "r"(addr));
}
__device__ __forceinline__ void mma16816(float* c, const uint32_t* a, const uint32_t* b) {
    asm volatile("mma.sync.aligned.m16n8k16.row.col.f32.f16.f16.f32 "
        "{%0,%1,%2,%3}, {%4,%5,%6,%7}, {%8,%9}, {%0,%1,%2,%3};"
        : "+f"(c[0]), "+f"(c[1]), "+f"(c[2]), "+f"(c[3])
        : "r"(a[0]), "r"(a[1]), "r"(a[2]), "r"(a[3]), "r"(b[0]), "r"(b[1]));
}

// ============ weight pre-conversion (once per call) ============
__global__ void cvt_weights(const float* __restrict__ w1a, const float* __restrict__ w2a,
                            const float* __restrict__ w1b, const float* __restrict__ w2b,
                            const float* __restrict__ wq, __half* __restrict__ o)
{
    int i = blockIdx.x * 256 + threadIdx.x;
    if (i >= 278528) return;
    float v;
    if (i < 65536) v = w1a[i];
    else if (i < 131072) v = w2a[i - 65536];
    else if (i < 196608) v = w1b[i - 131072];
    else if (i < 262144) v = w2b[i - 196608];
    else v = wq[i - 262144];
    o[i] = __float2half_rn(v);
}

// ---------------- shared smem layout ----------------
#define RPITCH 272
#define SM_X   0        // fp16 tile [128][RPITCH]
#define SM_W   34816
#define SM_H   69632
#define SM_PA  104448   // 128 float2
#define SM_PB  105472
#define SM_BUF 106496   // kernel B only: 1280 floats
#define SMEM_A 106496
#define SMEM_B 111616

// ======================================================================
// Kernel A: gather x -> MLP1 (fp16 mma) -> +x -> LN(g1) -> xproj
//           then qbuf = xproj @ w_q + b_q (extra GEMM in-CTA)
// 128 rows/CTA, 256 threads (8 warps, 2x4 grid of 64x32 tiles)
// ======================================================================
__global__ __launch_bounds__(256, 1) void fused_mlp1_qproj(
    const float* __restrict__ in,
    const __half* __restrict__ w1h, const float* __restrict__ b1,
    const __half* __restrict__ w2h, const float* __restrict__ b2,
    const float* __restrict__ ga, const float* __restrict__ ba,
    const __half* __restrict__ wqh, const float* __restrict__ bq,
    float* __restrict__ xproj, float* __restrict__ qbuf)
{
    extern __shared__ char smem[];
    const int tid = threadIdx.x;
    const int wid = tid >> 5;
    const int lane = tid & 31;
    const int R0 = blockIdx.x * 128;
    const int bl0 = R0 >> 10;
    const int bI = bl0 >> 5, lI = bl0 & 31, tb0 = R0 & 1023;
    const uint32_t sb = su32(smem);
    float2* partA = (float2*)(smem + SM_PA);
    float2* partB = (float2*)(smem + SM_PB);

    // ---- stage X fp16 (gathered) ----
#pragma unroll
    for (int i = 0; i < 16; i++) {
        int idx = tid + i * 256;
        int m = idx >> 5, k4 = (idx & 31) * 4;
        int grow = (((bI << 10) + tb0 + m) << 5) + lI;
        float4 v = *(const float4*)(in + grow * 128 + k4);
        *(ull*)(smem + SM_X + m * RPITCH + k4 * 2) = pack4h(v);
    }

    const int wm = (wid >> 2) * 64;
    const int wn = (wid & 3) * 32;
    const int l4 = lane >> 2, lc = (lane & 3) * 2;
    const uint32_t aoffs = (uint32_t)((((lane >> 3) & 1) * 8 + (lane & 7)) * RPITCH
                                      + (((lane >> 4) & 1) * 8) * 2);

    float o[4][4][4];
#pragma unroll
    for (int ni = 0; ni < 4; ni++) {
        int col = wn + ni * 8 + lc;
        float bv0 = __ldg(&b2[col]), bv1 = __ldg(&b2[col + 1]);
#pragma unroll
        for (int mi = 0; mi < 4; mi++) {
            o[mi][ni][0] = bv0; o[mi][ni][1] = bv1;
            o[mi][ni][2] = bv0; o[mi][ni][3] = bv1;
        }
    }

    for (int ch = 0; ch < 4; ch++) {
        __syncthreads();
#pragma unroll
        for (int i = 0; i < 8; i++) {
            int idx = tid + i * 256;
            int k = idx >> 4, j = idx & 15;
            *(int4*)(smem + SM_W + k * RPITCH + j * 16) =
                *(const int4*)(w1h + k * 512 + ch * 128 + j * 8);
        }
        __syncthreads();

        float h[4][4][4];
#pragma unroll
        for (int ni = 0; ni < 4; ni++) {
            int col = wn + ni * 8 + lc;
            float bv0 = __ldg(&b1[ch * 128 + col]), bv1 = __ldg(&b1[ch * 128 + col + 1]);
#pragma unroll
            for (int mi = 0; mi < 4; mi++) {
                h[mi][ni][0] = bv0; h[mi][ni][1] = bv1;
                h[mi][ni][2] = bv0; h[mi][ni][3] = bv1;
            }
        }
#pragma unroll 1
        for (int ks = 0; ks < 8; ks++) {
            int k0 = ks * 16;
            uint32_t a[4][4], b[8];
#pragma unroll
            for (int mi = 0; mi < 4; mi++)
                ldmx4(a[mi], sb + SM_X + (wm + mi * 16) * RPITCH + k0 * 2 + aoffs);
            ldmx4t(b,     sb + SM_W + k0 * RPITCH + wn * 2 + aoffs);
            ldmx4t(b + 4, sb + SM_W + k0 * RPITCH + (wn + 16) * 2 + aoffs);
#pragma unroll
            for (int mi = 0; mi < 4; mi++)
#pragma unroll
                for (int ni = 0; ni < 4; ni++)
                    mma16816(h[mi][ni], a[mi], b + 2 * ni);
        }
#pragma unroll
        for (int mi = 0; mi < 4; mi++)
#pragma unroll
            for (int ni = 0; ni < 4; ni++) {
                int r_ = wm + mi * 16 + l4;
                int cb = (wn + ni * 8 + lc) * 2;
                unsigned short h0 = __half_as_ushort(__float2half_rn(gelu_exact(h[mi][ni][0])));
                unsigned short h1 = __half_as_ushort(__float2half_rn(gelu_exact(h[mi][ni][1])));
                unsigned short h2 = __half_as_ushort(__float2half_rn(gelu_exact(h[mi][ni][2])));
                unsigned short h3 = __half_as_ushort(__float2half_rn(gelu_exact(h[mi][ni][3])));
                *(uint32_t*)(smem + SM_H + r_ * RPITCH + cb) = (uint32_t)h0 | ((uint32_t)h1 << 16);
                *(uint32_t*)(smem + SM_H + (r_ + 8) * RPITCH + cb) = (uint32_t)h2 | ((uint32_t)h3 << 16);
            }
        __syncthreads();
#pragma unroll
        for (int i = 0; i < 8; i++) {
            int idx = tid + i * 256;
            int k = idx >> 4, j = idx & 15;
            *(int4*)(smem + SM_W + k * RPITCH + j * 16) =
                *(const int4*)(w2h + (ch * 128 + k) * 128 + j * 8);
        }
        __syncthreads();
#pragma unroll 1
        for (int ks = 0; ks < 8; ks++) {
            int k0 = ks * 16;
            uint32_t a[4][4], b[8];
#pragma unroll
            for (int mi = 0; mi < 4; mi++)
                ldmx4(a[mi], sb + SM_H + (wm + mi * 16) * RPITCH + k0 * 2 + aoffs);
            ldmx4t(b,     sb + SM_W + k0 * RPITCH + wn * 2 + aoffs);
            ldmx4t(b + 4, sb + SM_W + k0 * RPITCH + (wn + 16) * 2 + aoffs);
#pragma unroll
            for (int mi = 0; mi < 4; mi++)
#pragma unroll
                for (int ni = 0; ni < 4; ni++)
                    mma16816(o[mi][ni], a[mi], b + 2 * ni);
        }
    }

    // ---- epilogue: dump -> +resid -> LN -> xproj ----
    __syncthreads();
    float* OB = (float*)(smem);                // [128][132]
#pragma unroll
    for (int mi = 0; mi < 4; mi++)
#pragma unroll
        for (int ni = 0; ni < 4; ni++) {
            int r_ = wm + mi * 16 + l4;
            int c_ = wn + ni * 8 + lc;
            *(float2*)(OB + r_ * 132 + c_) = make_float2(o[mi][ni][0], o[mi][ni][1]);
            *(float2*)(OB + (r_ + 8) * 132 + c_) = make_float2(o[mi][ni][2], o[mi][ni][3]);
        }
    __syncthreads();

    const int c0 = (wid >= 4) ? 64 : 0;
    const int m = ((wid & 3) << 5) + lane;
    float v[64];
    {
        int grow = (((bI << 10) + tb0 + m) << 5) + lI;
        const float* rp = in + grow * 128 + c0;
#pragma unroll
        for (int g = 0; g < 16; g++) {
            float4 u = *(const float4*)(rp + 4 * g);
            float4 a = *(const float4*)(OB + m * 132 + c0 + 4 * g);
            v[4 * g + 0] = a.x + u.x; v[4 * g + 1] = a.y + u.y;
            v[4 * g + 2] = a.z + u.z; v[4 * g + 3] = a.w + u.w;
        }
    }
    {
        float s = 0.f, q = 0.f;
#pragma unroll
        for (int j = 0; j < 64; j++) { s += v[j]; q += v[j] * v[j]; }
        if (c0 == 0) partA[m] = make_float2(s, q); else partB[m] = make_float2(s, q);
    }
    __syncthreads();
    {
        float2 pa = partA[m], pb = partB[m];
        float s = pa.x + pb.x, q = pa.y + pb.y;
        float mean = s * 0.0078125f;
        float rstd = rsqrtf(fmaxf(q * 0.0078125f - mean * mean, 0.f) + 1e-5f);
#pragma unroll
        for (int j = 0; j < 64; j++)
            v[j] = (v[j] - mean) * rstd * __ldg(&ga[c0 + j]) + __ldg(&ba[c0 + j]);
    }
    const int Rg = R0 + m;
#pragma unroll
    for (int g = 0; g < 16; g++)
        *(float4*)(xproj + Rg * 128 + c0 + 4 * g) =
            make_float4(v[4 * g], v[4 * g + 1], v[4 * g + 2], v[4 * g + 3]);
    __syncthreads();   // all OB reads done

    // ---- q-projection: restage LN output as fp16, GEMM vs w_q ----
#pragma unroll
    for (int g = 0; g < 16; g++)
        *(ull*)(smem + SM_X + m * RPITCH + (c0 + 4 * g) * 2) =
            pack4h(make_float4(v[4 * g], v[4 * g + 1], v[4 * g + 2], v[4 * g + 3]));
#pragma unroll
    for (int i = 0; i < 8; i++) {
        int idx = tid + i * 256;
        int k = idx >> 4, j = idx & 15;
        *(int4*)(smem + SM_W + k * RPITCH + j * 16) = *(const int4*)(wqh + k * 128 + j * 8);
    }
    __syncthreads();
#pragma unroll
    for (int ni = 0; ni < 4; ni++) {
        int col = wn + ni * 8 + lc;
        float bv0 = __ldg(&bq[col]), bv1 = __ldg(&bq[col + 1]);
#pragma unroll
        for (int mi = 0; mi < 4; mi++) {
            o[mi][ni][0] = bv0; o[mi][ni][1] = bv1;
            o[mi][ni][2] = bv0; o[mi][ni][3] = bv1;
        }
    }
#pragma unroll 1
    for (int ks = 0; ks < 8; ks++) {
        int k0 = ks * 16;
        uint32_t a[4][4], b[8];
#pragma unroll
        for (int mi = 0; mi < 4; mi++)
            ldmx4(a[mi], sb + SM_X + (wm + mi * 16) * RPITCH + k0 * 2 + aoffs);
        ldmx4t(b,     sb + SM_W + k0 * RPITCH + wn * 2 + aoffs);
        ldmx4t(b + 4, sb + SM_W + k0 * RPITCH + (wn + 16) * 2 + aoffs);
#pragma unroll
        for (int mi = 0; mi < 4; mi++)
#pragma unroll
            for (int ni = 0; ni < 4; ni++)
                mma16816(o[mi][ni], a[mi], b + 2 * ni);
    }
#pragma unroll
    for (int mi = 0; mi < 4; mi++)
#pragma unroll
        for (int ni = 0; ni < 4; ni++) {
            int r_ = R0 + wm + mi * 16 + l4;
            int c_ = wn + ni * 8 + lc;
            *(float2*)(qbuf + r_ * 128 + c_) = make_float2(o[mi][ni][0], o[mi][ni][1]);
            *(float2*)(qbuf + (r_ + 8) * 128 + c_) = make_float2(o[mi][ni][2], o[mi][ni][3]);
        }
}

// ======================================================================
// Kernel B: recv attention (in-CTA) -> MLP2 -> +xproj -> LN(g2) -> LN(g3)
//           -> scatter to out [B,T,L,D]
// ======================================================================
__global__ __launch_bounds__(256, 1) void fused_recv_mlp2(
    const float* __restrict__ qbuf, const float* __restrict__ bufp,
    const float* __restrict__ xproj,
    const __half* __restrict__ w1h, const float* __restrict__ b1,
    const __half* __restrict__ w2h, const float* __restrict__ b2,
    const float* __restrict__ ga, const float* __restrict__ ba,
    const float* __restrict__ gb, const float* __restrict__ bb,
    float* __restrict__ out)
{
    extern __shared__ char smem[];
    const int tid = threadIdx.x;
    const int wid = tid >> 5;
    const int lane = tid & 31;
    const int R0 = blockIdx.x * 128;
    const int bl0 = R0 >> 10;
    const int bI = bl0 >> 5, lI = bl0 & 31, tb0 = R0 & 1023;
    const uint32_t sb = su32(smem);
    float2* partA = (float2*)(smem + SM_PA);
    float2* partB = (float2*)(smem + SM_PB);
    float* BUFS = (float*)(smem + SM_BUF);   // [2][10][64]

    for (int idx = tid; idx < 1280; idx += 256)
        BUFS[idx] = bufp[bl0 * 1280 + idx];
    __syncthreads();

    // ---- recv attention: thread = (row r, head hd) ----
    {
        const int r = tid & 127, hd = tid >> 7;
        const int t = tb0 + r;
        const float* qr = qbuf + (R0 + r) * 128 + hd * 64;
        float q[64];
#pragma unroll
        for (int g = 0; g < 16; g++) {
            float4 u = *(const float4*)(qr + 4 * g);
            q[4 * g] = u.x; q[4 * g + 1] = u.y; q[4 * g + 2] = u.z; q[4 * g + 3] = u.w;
        }
        const float* BF = BUFS + hd * 640;
        float s[10];
#pragma unroll
        for (int j = 0; j < 10; j++) {
            float d = 0.f;
#pragma unroll
            for (int k = 0; k < 64; k++) d += q[k] * BF[j * 64 + k];
            s[j] = fminf(fmaxf(d * 0.125f, -CLAMPV), CLAMPV);
        }
        bool all = (t >= 10);
        float mx = -1e30f;
#pragma unroll
        for (int j = 0; j < 10; j++) {
            bool a = all || (j >= t - 5 && j <= t + 5);
            if (a) mx = fmaxf(mx, s[j]);
        }
        float p[10], den = 0.f;
#pragma unroll
        for (int j = 0; j < 10; j++) {
            bool a = all || (j >= t - 5 && j <= t + 5);
            p[j] = a ? expf(s[j] - mx) : 0.f;
            den += p[j];
        }
        float rinv = 1.f / den;
#pragma unroll
        for (int j = 0; j < 10; j++) p[j] *= rinv;
#pragma unroll
        for (int g = 0; g < 16; g++) {
            float4 acc = make_float4(0.f, 0.f, 0.f, 0.f);
#pragma unroll
            for (int j = 0; j < 10; j++) {
                float4 bv = *(const float4*)(BF + j * 64 + 4 * g);
                acc.x += p[j] * bv.x; acc.y += p[j] * bv.y;
                acc.z += p[j] * bv.z; acc.w += p[j] * bv.w;
            }
            *(ull*)(smem + SM_X + r * RPITCH + (hd * 64 + 4 * g) * 2) = pack4h(acc);
        }
    }

    const int wm = (wid >> 2) * 64;
    const int wn = (wid & 3) * 32;
    const int l4 = lane >> 2, lc = (lane & 3) * 2;
    const uint32_t aoffs = (uint32_t)((((lane >> 3) & 1) * 8 + (lane & 7)) * RPITCH
                                      + (((lane >> 4) & 1) * 8) * 2);

    float o[4][4][4];
#pragma unroll
    for (int ni = 0; ni < 4; ni++) {
        int col = wn + ni * 8 + lc;
        float bv0 = __ldg(&b2[col]), bv1 = __ldg(&b2[col + 1]);
#pragma unroll
        for (int mi = 0; mi < 4; mi++) {
            o[mi][ni][0] = bv0; o[mi][ni][1] = bv1;
            o[mi][ni][2] = bv0; o[mi][ni][3] = bv1;
        }
    }

    for (int ch = 0; ch < 4; ch++) {
        __syncthreads();
#pragma unroll
        for (int i = 0; i < 8; i++) {
            int idx = tid + i * 256;
            int k = idx >> 4, j = idx & 15;
            *(int4*)(smem + SM_W + k * RPITCH + j * 16) =
                *(const int4*)(w1h + k * 512 + ch * 128 + j * 8);
        }
        __syncthreads();

        float h[4][4][4];
#pragma unroll
        for (int ni = 0; ni < 4; ni++) {
            int col = wn + ni * 8 + lc;
            float bv0 = __ldg(&b1[ch * 128 + col]), bv1 = __ldg(&b1[ch * 128 + col + 1]);
#pragma unroll
            for (int mi = 0; mi < 4; mi++) {
                h[mi][ni][0] = bv0; h[mi][ni][1] = bv1;
                h[mi][ni][2] = bv0; h[mi][ni][3] = bv1;
            }
        }
#pragma unroll 1
        for (int ks = 0; ks < 8; ks++) {
            int k0 = ks * 16;
            uint32_t a[4][4], b[8];
#pragma unroll
            for (int mi = 0; mi < 4; mi++)
                ldmx4(a[mi], sb + SM_X + (wm + mi * 16) * RPITCH + k0 * 2 + aoffs);
            ldmx4t(b,     sb + SM_W + k0 * RPITCH + wn * 2 + aoffs);
            ldmx4t(b + 4, sb + SM_W + k0 * RPITCH + (wn + 16) * 2 + aoffs);
#pragma unroll
            for (int mi = 0; mi < 4; mi++)
#pragma unroll
                for (int ni = 0; ni < 4; ni++)
                    mma16816(h[mi][ni], a[mi], b + 2 * ni);
        }
#pragma unroll
        for (int mi = 0; mi < 4; mi++)
#pragma unroll
            for (int ni = 0; ni < 4; ni++) {
                int r_ = wm + mi * 16 + l4;
                int cb = (wn + ni * 8 + lc) * 2;
                unsigned short h0 = __half_as_ushort(__float2half_rn(gelu_exact(h[mi][ni][0])));
                unsigned short h1 = __half_as_ushort(__float2half_rn(gelu_exact(h[mi][ni][1])));
                unsigned short h2 = __half_as_ushort(__float2half_rn(gelu_exact(h[mi][ni][2])));
                unsigned short h3 = __half_as_ushort(__float2half_rn(gelu_exact(h[mi][ni][3])));
                *(uint32_t*)(smem + SM_H + r_ * RPITCH + cb) = (uint32_t)h0 | ((uint32_t)h1 << 16);
                *(uint32_t*)(smem + SM_H + (r_ + 8) * RPITCH + cb) = (uint32_t)h2 | ((uint32_t)h3 << 16);
            }
        __syncthreads();
#pragma unroll
        for (int i = 0; i < 8; i++) {
            int idx = tid + i * 256;
            int k = idx >> 4, j = idx & 15;
            *(int4*)(smem + SM_W + k * RPITCH + j * 16) =
                *(const int4*)(w2h + (ch * 128 + k) * 128 + j * 8);
        }
        __syncthreads();
#pragma unroll 1
        for (int ks = 0; ks < 8; ks++) {
            int k0 = ks * 16;
            uint32_t a[4][4], b[8];
#pragma unroll
            for (int mi = 0; mi < 4; mi++)
                ldmx4(a[mi], sb + SM_H + (wm + mi * 16) * RPITCH + k0 * 2 + aoffs);
            ldmx4t(b,     sb + SM_W + k0 * RPITCH + wn * 2 + aoffs);
            ldmx4t(b + 4, sb + SM_W + k0 * RPITCH + (wn + 16) * 2 + aoffs);
#pragma unroll
            for (int mi = 0; mi < 4; mi++)
#pragma unroll
                for (int ni = 0; ni < 4; ni++)
                    mma16816(o[mi][ni], a[mi], b + 2 * ni);
        }
    }

    // ---- epilogue: +xproj, LN(g2), LN(g3), scatter ----
    __syncthreads();
    float* OB = (float*)(smem);
#pragma unroll
    for (int mi = 0; mi < 4; mi++)
#pragma unroll
        for (int ni = 0; ni < 4; ni++) {
            int r_ = wm + mi * 16 + l4;
            int c_ = wn + ni * 8 + lc;
            *(float2*)(OB + r_ * 132 + c_) = make_float2(o[mi][ni][0], o[mi][ni][1]);
            *(float2*)(OB + (r_ + 8) * 132 + c_) = make_float2(o[mi][ni][2], o[mi][ni][3]);
        }
    __syncthreads();

    const int c0 = (wid >= 4) ? 64 : 0;
    const int m = ((wid & 3) << 5) + lane;
    float v[64];
    {
        const float* rp = xproj + (R0 + m) * 128 + c0;
#pragma unroll
        for (int g = 0; g < 16; g++) {
            float4 u = *(const float4*)(rp + 4 * g);
            float4 a = *(const float4*)(OB + m * 132 + c0 + 4 * g);
            v[4 * g + 0] = a.x + u.x; v[4 * g + 1] = a.y + u.y;
            v[4 * g + 2] = a.z + u.z; v[4 * g + 3] = a.w + u.w;
        }
    }
    {
        float s = 0.f, q = 0.f;
#pragma unroll
        for (int j = 0; j < 64; j++) { s += v[j]; q += v[j] * v[j]; }
        if (c0 == 0) partA[m] = make_float2(s, q); else partB[m] = make_float2(s, q);
    }
    __syncthreads();
    {
        float2 pa = partA[m], pb = partB[m];
        float s = pa.x + pb.x, q = pa.y + pb.y;
        float mean = s * 0.0078125f;
        float rstd = rsqrtf(fmaxf(q * 0.0078125f - mean * mean, 0.f) + 1e-5f);
#pragma unroll
        for (int j = 0; j < 64; j++)
            v[j] = (v[j] - mean) * rstd * __ldg(&ga[c0 + j]) + __ldg(&ba[c0 + j]);
    }
    __syncthreads();
    {
        float s = 0.f, q = 0.f;
#pragma unroll
        for (int j = 0; j < 64; j++) { s += v[j]; q += v[j] * v[j]; }
        if (c0 == 0) partA[m] = make_float2(s, q); else partB[m] = make_float2(s, q);
    }
    __syncthreads();
    float2 pa = partA[m], pb = partB[m];
    float s = pa.x + pb.x, q = pa.y + pb.y;
    float m2 = s * 0.0078125f;
    float rstd2 = rsqrtf(fmaxf(q * 0.0078125f - m2 * m2, 0.f) + 1e-5f);
    int t = tb0 + m;
    int ob = (((bI << 10) + t) * 32 + lI) * 128;
#pragma unroll
    for (int g = 0; g < 16; g++) {
        float4 w;
        w.x = (v[4 * g + 0] - m2) * rstd2 * __ldg(&gb[c0 + 4 * g + 0]) + __ldg(&bb[c0 + 4 * g + 0]);
        w.y = (v[4 * g + 1] - m2) * rstd2 * __ldg(&gb[c0 + 4 * g + 1]) + __ldg(&bb[c0 + 4 * g + 1]);
        w.z = (v[4 * g + 2] - m2) * rstd2 * __ldg(&gb[c0 + 4 * g + 2]) + __ldg(&bb[c0 + 4 * g + 2]);
        w.w = (v[4 * g + 3] - m2) * rstd2 * __ldg(&gb[c0 + 4 * g + 3]) + __ldg(&bb[c0 + 4 * g + 3]);
        *(float4*)(out + ob + c0 + 4 * g) = w;
    }
}

// ============ K/V projection, t<15 only ============
#define SMEM_KV (34688 * 4)
__global__ __launch_bounds__(256, 1) void kv_kernel(
    const float* __restrict__ xp,
    const float* __restrict__ wk, const float* __restrict__ bk,
    const float* __restrict__ wv, const float* __restrict__ bv,
    float* __restrict__ k15, float* __restrict__ v15)
{
    extern __shared__ float sm[];
    float* Xs = sm;
    float* Wks = sm + 1920;
    float* Wvs = sm + 18304;
    const int bl = blockIdx.x, tid = threadIdx.x;
    for (int idx = tid; idx < 1920; idx += 256)
        Xs[idx] = xp[(bl * 1024 + (idx >> 7)) * 128 + (idx & 127)];
    for (int idx = tid; idx < 16384; idx += 256) { Wks[idx] = wk[idx]; Wvs[idx] = wv[idx]; }
    __syncthreads();
    const int m = tid >> 7, n = tid & 127;
    const float* W = m ? Wvs : Wks;
    const float bsv = m ? __ldg(&bv[n]) : __ldg(&bk[n]);
    float* o = m ? v15 : k15;
    for (int t = 0; t < 15; t++) {
        float acc = bsv;
#pragma unroll 8
        for (int k = 0; k < 128; k++) acc += Xs[t * 128 + k] * W[k * 128 + n];
        o[(bl * 15 + t) * 128 + n] = acc;
    }
}

// ============ router projection ============
__global__ void rproj_kernel(const float* __restrict__ router,
                             const float* __restrict__ w,
                             const float* __restrict__ b,
                             float* __restrict__ rp)
{
    __shared__ float rs[128];
    const int row = blockIdx.x, tid = threadIdx.x;
    rs[tid] = router[row * 128 + tid];
    __syncthreads();
    float acc = __ldg(&b[tid]);
#pragma unroll 8
    for (int k = 0; k < 128; k++) acc += rs[k] * w[k * 128 + tid];
    rp[row * 128 + tid] = acc;
}

// ============ buffer attention ============
__global__ void buffer_kernel(const float* __restrict__ rp,
                              const float* __restrict__ k15,
                              const float* __restrict__ v15,
                              float* __restrict__ buf)
{
    __shared__ float qs[10][64], ks[15][64], vs[15][64], sw[16];
    const int bl = blockIdx.x >> 1, h = blockIdx.x & 1;
    const int tid = threadIdx.x;
    const int l = bl & 31;
    for (int idx = tid; idx < 640; idx += 64)
        qs[idx >> 6][idx & 63] = rp[(l * 10 + (idx >> 6)) * 128 + h * 64 + (idx & 63)];
    for (int idx = tid; idx < 960; idx += 64) {
        int base = (bl * 15 + (idx >> 6)) * 128 + h * 64 + (idx & 63);
        ks[idx >> 6][idx & 63] = k15[base];
        vs[idx >> 6][idx & 63] = v15[base];
    }
    __syncthreads();
    for (int i = 0; i < 10; i++) {
        int jlo = (i > 5) ? (i - 5) : 0;
        int cnt = i + 5 - jlo + 1;
        if (tid < cnt) {
            float s = 0.f;
            const float* q = qs[i]; const float* kk = ks[jlo + tid];
#pragma unroll 8
            for (int d = 0; d < 64; d++) s += q[d] * kk[d];
            s *= 0.125f;
            sw[tid] = fminf(fmaxf(s, -CLAMPV), CLAMPV);
        }
        __syncthreads();
        float mm = -1e30f;
        for (int j = 0; j < cnt; j++) mm = fmaxf(mm, sw[j]);
        float den = 0.f, o = 0.f;
        for (int j = 0; j < cnt; j++) {
            float p = expf(sw[j] - mm);
            den += p;
            o += p * vs[jlo + j][tid];
        }
        buf[((bl * 2 + h) * 10 + i) * 64 + tid] = o / den;
        __syncthreads();
    }
}

// ============ launch ============
extern "C" void kernel_launch(void* const* d_in, const int* in_sizes, int n_in,
                              void* d_out, int out_size)
{
    const float* x        = (const float*)d_in[0];
    const float* router   = (const float*)d_in[1];
    const float* w_router = (const float*)d_in[2];
    const float* b_router = (const float*)d_in[3];
    const float* w_k      = (const float*)d_in[4];
    const float* b_k      = (const float*)d_in[5];
    const float* w_v      = (const float*)d_in[6];
    const float* b_v      = (const float*)d_in[7];
    const float* w_q      = (const float*)d_in[8];
    const float* b_q      = (const float*)d_in[9];
    const float* m1w1 = (const float*)d_in[10];
    const float* m1b1 = (const float*)d_in[11];
    const float* m1w2 = (const float*)d_in[12];
    const float* m1b2 = (const float*)d_in[13];
    const float* m2w1 = (const float*)d_in[14];
    const float* m2b1 = (const float*)d_in[15];
    const float* m2w2 = (const float*)d_in[16];
    const float* m2b2 = (const float*)d_in[17];
    const float* g1  = (const float*)d_in[18];
    const float* be1 = (const float*)d_in[19];
    const float* g2  = (const float*)d_in[20];
    const float* be2 = (const float*)d_in[21];
    const float* g3  = (const float*)d_in[22];
    const float* be3 = (const float*)d_in[23];
    float* out = (float*)d_out;

    float *xproj, *qbuf, *k15, *v15, *rproj, *bufp;
    __half* w16;
    cudaGetSymbolAddress((void**)&xproj, g_xproj);
    cudaGetSymbolAddress((void**)&qbuf,  g_qbuf);
    cudaGetSymbolAddress((void**)&k15,   g_k15);
    cudaGetSymbolAddress((void**)&v15,   g_v15);
    cudaGetSymbolAddress((void**)&rproj, g_rproj);
    cudaGetSymbolAddress((void**)&bufp,  g_buf);
    cudaGetSymbolAddress((void**)&w16,   g_w16);

    cudaFuncSetAttribute(fused_mlp1_qproj, cudaFuncAttributeMaxDynamicSharedMemorySize, SMEM_A);
    cudaFuncSetAttribute(fused_recv_mlp2, cudaFuncAttributeMaxDynamicSharedMemorySize, SMEM_B);
    cudaFuncSetAttribute(kv_kernel, cudaFuncAttributeMaxDynamicSharedMemorySize, SMEM_KV);

    // 0. weights -> fp16
    cvt_weights<<<1088, 256>>>(m1w1, m1w2, m2w1, m2w2, w_q, w16);
    // 1. x_proj = LN(x + mlp1(x)); qbuf = x_proj @ w_q + b_q
    fused_mlp1_qproj<<<1024, 256, SMEM_A>>>(
        x, w16, m1b1, w16 + 65536, m1b2, g1, be1, w16 + 262144, b_q, xproj, qbuf);
    // 2. K/V for t<15
    kv_kernel<<<128, 256, SMEM_KV>>>(xproj, w_k, b_k, w_v, b_v, k15, v15);
    // 3. router projection
    rproj_kernel<<<320, 128>>>(router, w_router, b_router, rproj);
    // 4. buffer attention
    buffer_kernel<<<256, 64>>>(rproj, k15, v15, bufp);
    // 5. recv attention + mlp2 + LN2 + LN3 + scatter
    fused_recv_mlp2<<<1024, 256, SMEM_B>>>(
        qbuf, bufp, xproj, w16 + 131072, m2b1, w16 + 196608, m2b2,
        g2, be2, g3, be3, out);
}